// round 4
// baseline (speedup 1.0000x reference)
#include <cuda_runtime.h>
#include <cuda_bf16.h>
#include <math.h>

#define VV 32000
#define EE 64
#define HH 128
#define SS 1024
#define BB 128
#define TT 64
#define GG 384

// ---------------- device scratch (no allocs) ----------------
__device__ float g_gi[(size_t)SS*BB*GG];       // encoder input projections [s*B+b][g]
__device__ float g_enc_out[(size_t)SS*BB*HH];  // [s][b][h]
__device__ float g_enc_proj[(size_t)SS*BB*HH]; // [s][b][h]
__device__ float g_outWT[(size_t)256*VV];      // out_W transposed [k][v]
__device__ float g_h[BB*HH];                   // decoder hidden [b][h]
__device__ float g_hT[HH*BB];                  // transposed [h][b]
__device__ float g_xgruT[192*BB];              // [emb(64);ctx(128)] x [b]
__device__ float g_xlogT[256*BB];              // [h2(128);ctx(128)] x [b]
__device__ float g_gdi[GG*BB];
__device__ float g_gdh[GG*BB];

__device__ __forceinline__ float sig_acc(float x){ return 1.0f/(1.0f + expf(-x)); }
__device__ __forceinline__ float tanh_fast(float x){
  // accurate to ~1e-6: tanh(x) = 1 - 2/(exp(2x)+1)
  return 1.0f - __fdividef(2.0f, __expf(2.0f*x) + 1.0f);
}

// ---------------- setup: transpose out_W ----------------
__global__ void k_transp(const float* __restrict__ outW){
  __shared__ float tile[32][33];
  int v0 = blockIdx.x*32, k0 = blockIdx.y*32;
  int tx = threadIdx.x, ty = threadIdx.y;
  #pragma unroll
  for(int i=0;i<32;i+=8)
    tile[ty+i][tx] = outW[(size_t)(v0+ty+i)*256 + k0+tx];
  __syncthreads();
  #pragma unroll
  for(int i=0;i<32;i+=8)
    g_outWT[(size_t)(k0+ty+i)*VV + v0+tx] = tile[tx][ty+i];
}

// ---------------- setup: first decoder token embedding ----------------
__global__ void k_emb0(const int* __restrict__ seq, const float* __restrict__ emb){
  int k = blockIdx.x;      // 0..63
  int b = threadIdx.x;     // 0..127
  int tok = seq[b];        // seq[0][b]
  g_xgruT[k*BB + b] = emb[(size_t)tok*EE + k];
}

// ---------------- encoder input projection ----------------
__global__ void __launch_bounds__(384,2) k_giall(const int* __restrict__ seq,
      const float* __restrict__ emb, const float* __restrict__ Wih,
      const float* __restrict__ bih){
  int g = threadIdx.x;
  float w[64];
  const float4* wp = (const float4*)(Wih + (size_t)g*64);
  #pragma unroll
  for(int i=0;i<16;i++){ float4 q=wp[i]; w[4*i]=q.x; w[4*i+1]=q.y; w[4*i+2]=q.z; w[4*i+3]=q.w; }
  float bias = bih[g];
  __shared__ float xs[2][64];
  const int ROWS = (SS*BB)/512;   // 256
  size_t base = (size_t)blockIdx.x * ROWS;
  if(g<64){ int tok0 = seq[base]; xs[0][g] = emb[(size_t)tok0*EE + g]; }
  __syncthreads();
  for(int r=0;r<ROWS;r++){
    int cur=r&1, nxt=cur^1;
    if(r+1<ROWS && g<64){
      int tok2 = seq[base+r+1];
      xs[nxt][g] = emb[(size_t)tok2*EE + g];
    }
    float a0=0,a1=0,a2=0,a3=0;
    #pragma unroll
    for(int k=0;k<64;k+=4){
      a0 += w[k]*xs[cur][k];     a1 += w[k+1]*xs[cur][k+1];
      a2 += w[k+2]*xs[cur][k+2]; a3 += w[k+3]*xs[cur][k+3];
    }
    g_gi[(base+r)*GG + g] = (a0+a1)+(a2+a3) + bias;
    __syncthreads();
  }
}

// ---------------- encoder recurrence: one CTA per batch row ----------------
__global__ void __launch_bounds__(384,1) k_encrec(const float* __restrict__ Whh,
      const float* __restrict__ bhh){
  extern __shared__ float sm[];
  float* whh_s = sm;            // 8*384 float4 = 12288 floats (k=96..127 transposed)
  float* hs    = sm + 12288;    // 128
  float* ghs   = hs + 128;      // 384
  float* gis   = ghs + 384;     // 384
  int b = blockIdx.x;
  int g = threadIdx.x;
  float w[96];
  {
    const float4* wlo = (const float4*)(Whh + (size_t)g*128);
    #pragma unroll
    for(int i=0;i<24;i++){ float4 q=wlo[i]; w[4*i]=q.x; w[4*i+1]=q.y; w[4*i+2]=q.z; w[4*i+3]=q.w; }
    const float4* whi = (const float4*)(Whh + (size_t)g*128 + 96);
    #pragma unroll
    for(int i=0;i<8;i++) ((float4*)whh_s)[i*384 + g] = whi[i];
  }
  float bias = bhh[g];
  if(g<128) hs[g] = 0.0f;
  __syncthreads();

  float giv = g_gi[(size_t)b*GG + g];   // s=0
  for(int s=0;s<SS;s++){
    float gi_next = 0.0f;
    if(s+1<SS) gi_next = g_gi[((size_t)(s+1)*BB + b)*GG + g];
    gis[g] = giv;
    float a0=0,a1=0,a2=0,a3=0;
    #pragma unroll
    for(int i=0;i<24;i++){
      float4 hv = ((float4*)hs)[i];
      a0 += w[4*i]*hv.x;   a1 += w[4*i+1]*hv.y;
      a2 += w[4*i+2]*hv.z; a3 += w[4*i+3]*hv.w;
    }
    #pragma unroll
    for(int i=0;i<8;i++){
      float4 wv = ((float4*)whh_s)[i*384 + g];
      float4 hv = ((float4*)hs)[24 + i];
      a0 += wv.x*hv.x; a1 += wv.y*hv.y; a2 += wv.z*hv.z; a3 += wv.w*hv.w;
    }
    ghs[g] = (a0+a1)+(a2+a3) + bias;
    __syncthreads();
    if(g<128){
      float rr = sig_acc(gis[g]       + ghs[g]);
      float zz = sig_acc(gis[128+g]   + ghs[128+g]);
      float nn = tanhf (gis[256+g] + rr*ghs[256+g]);
      float hn = (1.0f-zz)*nn + zz*hs[g];
      g_enc_out[((size_t)s*BB + b)*HH + g] = hn;
      hs[g] = hn;
    }
    __syncthreads();
    giv = gi_next;
  }
  if(g<128){
    g_h[b*HH + g]  = hs[g];
    g_hT[g*BB + b] = hs[g];
  }
}

// ---------------- enc_proj = enc_out @ attn_W[:,128:].T + attn_b ----------------
__global__ void __launch_bounds__(256,2) k_encproj(const float* __restrict__ attnW,
                                                   const float* __restrict__ attnb){
  int t = threadIdx.x;
  int j = t & 127, half = t >> 7;
  float w[64];
  const float4* wp = (const float4*)(attnW + (size_t)j*256 + 128 + half*64);
  #pragma unroll
  for(int i=0;i<16;i++){ float4 q=wp[i]; w[4*i]=q.x; w[4*i+1]=q.y; w[4*i+2]=q.z; w[4*i+3]=q.w; }
  float bias = attnb[j];
  __shared__ float xs[2][128];
  __shared__ float part[2][128];
  const int ROWS = (SS*BB)/512;   // 256
  size_t base = (size_t)blockIdx.x * ROWS;
  if(t<128) xs[0][t] = g_enc_out[base*HH + t];
  __syncthreads();
  for(int r=0;r<ROWS;r++){
    int cur=r&1, nxt=cur^1;
    if(r+1<ROWS && t<128) xs[nxt][t] = g_enc_out[(base+r+1)*HH + t];
    float a0=0,a1=0,a2=0,a3=0;
    const float* xp = &xs[cur][half*64];
    #pragma unroll
    for(int k=0;k<64;k+=4){
      a0+=w[k]*xp[k]; a1+=w[k+1]*xp[k+1]; a2+=w[k+2]*xp[k+2]; a3+=w[k+3]*xp[k+3];
    }
    part[half][j] = (a0+a1)+(a2+a3);
    __syncthreads();
    if(!half) g_enc_proj[(base+r)*HH + j] = part[0][j] + part[1][j] + bias;
    __syncthreads();
  }
}

// ---------------- decoder: fused hp + scores + softmax + context ----------------
__global__ void __launch_bounds__(256,1) k_att(const float* __restrict__ attnW,
                                               const float* __restrict__ attnv){
  __shared__ float hs[128], hp[128], part[128], vsd[128];
  __shared__ float ws[1024];
  __shared__ float red[40];
  __shared__ float4 cbuf[8][32];
  int b = blockIdx.x, t = threadIdx.x;
  int lane = t&31, warp = t>>5;
  if(t<128){ hs[t] = g_h[b*HH + t]; vsd[t] = attnv[t]; }
  __syncthreads();
  // hp = h @ attn_W[:, :128].T
  {
    int j = t & 127, half = t >> 7;
    const float4* wr = (const float4*)(attnW + (size_t)j*256 + half*64);
    const float* hb = &hs[half*64];
    float a = 0.0f;
    #pragma unroll
    for(int i=0;i<16;i++){
      float4 q = wr[i];
      a += q.x*hb[4*i] + q.y*hb[4*i+1] + q.z*hb[4*i+2] + q.w*hb[4*i+3];
    }
    if(half) part[j] = a;
    __syncthreads();
    if(!half) hp[j] = a + part[j];
    __syncthreads();
  }
  // scores
  {
    float4 hq = ((float4*)hp)[lane];
    float4 vq = ((float4*)vsd)[lane];
    for(int s = warp; s < SS; s += 8){
      float4 e = ((const float4*)(g_enc_proj + ((size_t)s*BB + b)*HH))[lane];
      float sum = tanh_fast(e.x+hq.x)*vq.x + tanh_fast(e.y+hq.y)*vq.y
                + tanh_fast(e.z+hq.z)*vq.z + tanh_fast(e.w+hq.w)*vq.w;
      #pragma unroll
      for(int o=16;o;o>>=1) sum += __shfl_xor_sync(0xffffffffu, sum, o);
      if(lane==0) ws[s] = sum;
    }
  }
  __syncthreads();
  // softmax (unnormalized exps in ws; inv computed once)
  {
    float4 sc = ((float4*)ws)[t];
    float m = fmaxf(fmaxf(sc.x,sc.y), fmaxf(sc.z,sc.w));
    #pragma unroll
    for(int o=16;o;o>>=1) m = fmaxf(m, __shfl_xor_sync(0xffffffffu,m,o));
    if(lane==0) red[warp] = m;
    __syncthreads();
    if(t==0){ float mm=red[0]; for(int i=1;i<8;i++) mm=fmaxf(mm,red[i]); red[8]=mm; }
    __syncthreads();
    float M = red[8];
    float4 e;
    e.x=expf(sc.x-M); e.y=expf(sc.y-M); e.z=expf(sc.z-M); e.w=expf(sc.w-M);
    ((float4*)ws)[t] = e;
    float ssum = (e.x+e.y)+(e.z+e.w);
    #pragma unroll
    for(int o=16;o;o>>=1) ssum += __shfl_xor_sync(0xffffffffu, ssum, o);
    if(lane==0) red[16+warp] = ssum;
    __syncthreads();
    if(t==0){ float s2=0; for(int i=0;i<8;i++) s2+=red[16+i]; red[24]=s2; }
    __syncthreads();
  }
  float inv = 1.0f / red[24];
  // context = (1/Z) * sum_s ws[s] * enc_out[s,b,:]
  {
    int hq = t&31, sg = t>>5;
    float4 acc = make_float4(0,0,0,0);
    #pragma unroll 4
    for(int i=0;i<128;i++){
      int s = sg + (i<<3);
      float wg = ws[s];
      float4 ev = ((const float4*)(g_enc_out + ((size_t)s*BB + b)*HH))[hq];
      acc.x += wg*ev.x; acc.y += wg*ev.y; acc.z += wg*ev.z; acc.w += wg*ev.w;
    }
    cbuf[sg][hq] = acc;
    __syncthreads();
    if(t<32){
      float4 tot = cbuf[0][t];
      #pragma unroll
      for(int g2=1;g2<8;g2++){
        float4 c = cbuf[g2][t];
        tot.x+=c.x; tot.y+=c.y; tot.z+=c.z; tot.w+=c.w;
      }
      tot.x*=inv; tot.y*=inv; tot.z*=inv; tot.w*=inv;
      int h0 = t*4;
      float vals[4] = {tot.x, tot.y, tot.z, tot.w};
      #pragma unroll
      for(int jj=0;jj<4;jj++){
        float val = vals[jj];
        g_xgruT[(64 + h0+jj)*BB + b]  = val;
        g_xlogT[(128 + h0+jj)*BB + b] = val;
      }
    }
  }
}

// ---------------- decoder GRU gate GEMVs ----------------
__global__ void __launch_bounds__(128,4) k_dgates(const float* __restrict__ dWih,
      const float* __restrict__ dWhh, const float* __restrict__ dbih,
      const float* __restrict__ dbhh){
  __shared__ float wi[4][192], wh[4][128];
  int b = threadIdx.x;
  int g0 = blockIdx.x*4;
  for(int i=threadIdx.x; i<4*192; i+=128) wi[i/192][i%192] = dWih[(size_t)(g0 + i/192)*192 + (i%192)];
  for(int i=threadIdx.x; i<4*128; i+=128) wh[i/128][i%128] = dWhh[(size_t)(g0 + i/128)*128 + (i%128)];
  __syncthreads();
  float ai0=dbih[g0], ai1=dbih[g0+1], ai2=dbih[g0+2], ai3=dbih[g0+3];
  float ah0=dbhh[g0], ah1=dbhh[g0+1], ah2=dbhh[g0+2], ah3=dbhh[g0+3];
  #pragma unroll 4
  for(int k=0;k<192;k++){
    float xv = g_xgruT[k*BB + b];
    ai0 += wi[0][k]*xv; ai1 += wi[1][k]*xv; ai2 += wi[2][k]*xv; ai3 += wi[3][k]*xv;
  }
  #pragma unroll 4
  for(int k=0;k<128;k++){
    float hv = g_hT[k*BB + b];
    ah0 += wh[0][k]*hv; ah1 += wh[1][k]*hv; ah2 += wh[2][k]*hv; ah3 += wh[3][k]*hv;
  }
  g_gdi[(g0+0)*BB+b]=ai0; g_gdi[(g0+1)*BB+b]=ai1; g_gdi[(g0+2)*BB+b]=ai2; g_gdi[(g0+3)*BB+b]=ai3;
  g_gdh[(g0+0)*BB+b]=ah0; g_gdh[(g0+1)*BB+b]=ah1; g_gdh[(g0+2)*BB+b]=ah2; g_gdh[(g0+3)*BB+b]=ah3;
}

// ---------------- decoder GRU combine ----------------
__global__ void __launch_bounds__(128,8) k_dcombine(){
  int b = blockIdx.x, h = threadIdx.x;
  float ir = g_gdi[h*BB+b],  iz = g_gdi[(128+h)*BB+b], in_ = g_gdi[(256+h)*BB+b];
  float hr = g_gdh[h*BB+b],  hz = g_gdh[(128+h)*BB+b], hn  = g_gdh[(256+h)*BB+b];
  float rr = sig_acc(ir+hr), zz = sig_acc(iz+hz);
  float nn = tanhf(in_ + rr*hn);
  float hold = g_h[b*HH + h];
  float hnew = (1.0f-zz)*nn + zz*hold;
  g_h[b*HH + h]   = hnew;
  g_hT[h*BB + b]  = hnew;
  g_xlogT[h*BB + b] = hnew;
}

// ---------------- logits GEMM: out[t][b][v] = xlog[b] . outWT[:,v] + out_b[v] ----------------
#define LOG_SMEM ((256*128 + 64*64) * 4)
__global__ void __launch_bounds__(256,1) k_logits(const float* __restrict__ outb,
                                                  float* __restrict__ out, int t){
  extern __shared__ float sm[];
  float4* wb4 = (float4*)sm;                 // [64][16] float4 = 64x64 floats
  float4* Xs4 = (float4*)(sm + 64*64);       // [256][32] float4 = 256x128 floats
  int tid = threadIdx.x;
  int vg = tid & 15, bg = tid >> 4;          // vg: 4 v's, bg: 8 b's
  // load X (g_xlogT is already [k][b])
  {
    const float4* src = (const float4*)g_xlogT;
    #pragma unroll
    for(int j=0;j<32;j++) Xs4[tid + j*256] = src[tid + j*256];
  }
  float* outRow = out + (size_t)t*BB*VV;
  for(int tile = blockIdx.x; tile < VV/64; tile += 148){
    int v0 = tile*64;
    float4 acc[8];
    #pragma unroll
    for(int i=0;i<8;i++) acc[i] = make_float4(0,0,0,0);
    for(int c=0;c<4;c++){
      int k0 = c*64;
      __syncthreads();
      // cooperative load of WT chunk [64][64]
      #pragma unroll
      for(int j=0;j<4;j++){
        int idx = tid + j*256;                // f4 index in chunk
        int kk = idx >> 4, cc = idx & 15;
        wb4[idx] = *(const float4*)(g_outWT + (size_t)(k0+kk)*VV + v0 + cc*4);
      }
      __syncthreads();
      #pragma unroll 8
      for(int kk=0;kk<64;kk++){
        float4 wv = wb4[kk*16 + vg];
        float4 x0 = Xs4[(k0+kk)*32 + bg*2];
        float4 x1 = Xs4[(k0+kk)*32 + bg*2 + 1];
        acc[0].x += x0.x*wv.x; acc[0].y += x0.x*wv.y; acc[0].z += x0.x*wv.z; acc[0].w += x0.x*wv.w;
        acc[1].x += x0.y*wv.x; acc[1].y += x0.y*wv.y; acc[1].z += x0.y*wv.z; acc[1].w += x0.y*wv.w;
        acc[2].x += x0.z*wv.x; acc[2].y += x0.z*wv.y; acc[2].z += x0.z*wv.z; acc[2].w += x0.z*wv.w;
        acc[3].x += x0.w*wv.x; acc[3].y += x0.w*wv.y; acc[3].z += x0.w*wv.z; acc[3].w += x0.w*wv.w;
        acc[4].x += x1.x*wv.x; acc[4].y += x1.x*wv.y; acc[4].z += x1.x*wv.z; acc[4].w += x1.x*wv.w;
        acc[5].x += x1.y*wv.x; acc[5].y += x1.y*wv.y; acc[5].z += x1.y*wv.z; acc[5].w += x1.y*wv.w;
        acc[6].x += x1.z*wv.x; acc[6].y += x1.z*wv.y; acc[6].z += x1.z*wv.z; acc[6].w += x1.z*wv.w;
        acc[7].x += x1.w*wv.x; acc[7].y += x1.w*wv.y; acc[7].z += x1.w*wv.z; acc[7].w += x1.w*wv.w;
      }
    }
    float4 bb = *(const float4*)(outb + v0 + vg*4);
    #pragma unroll
    for(int i=0;i<8;i++){
      int b = bg*8 + i;
      float4 r;
      r.x = acc[i].x + bb.x; r.y = acc[i].y + bb.y;
      r.z = acc[i].z + bb.z; r.w = acc[i].w + bb.w;
      *(float4*)(outRow + (size_t)b*VV + v0 + vg*4) = r;
    }
  }
}

// ---------------- argmax + feedback embedding ----------------
__global__ void __launch_bounds__(256,1) k_argmax(const float* __restrict__ out,
      const float* __restrict__ emb, int t){
  __shared__ float sval[8];
  __shared__ int   sidx[8];
  __shared__ int   stok;
  int b = blockIdx.x, tid = threadIdx.x;
  int lane = tid&31, warp = tid>>5;
  const float* row = out + (size_t)t*BB*VV + (size_t)b*VV;
  float best = -1e38f; int bi = 0;
  for(int v4 = tid; v4 < VV/4; v4 += 256){
    float4 q = ((const float4*)row)[v4];
    int v = v4*4;
    if(q.x > best){ best=q.x; bi=v; }
    if(q.y > best){ best=q.y; bi=v+1; }
    if(q.z > best){ best=q.z; bi=v+2; }
    if(q.w > best){ best=q.w; bi=v+3; }
  }
  #pragma unroll
  for(int o=16;o;o>>=1){
    float ov = __shfl_xor_sync(0xffffffffu, best, o);
    int   oi = __shfl_xor_sync(0xffffffffu, bi,   o);
    if(ov > best || (ov == best && oi < bi)){ best = ov; bi = oi; }
  }
  if(lane==0){ sval[warp]=best; sidx[warp]=bi; }
  __syncthreads();
  if(tid==0){
    float bv = sval[0]; int bx = sidx[0];
    for(int i=1;i<8;i++){
      if(sval[i] > bv || (sval[i]==bv && sidx[i]<bx)){ bv=sval[i]; bx=sidx[i]; }
    }
    stok = bx;
  }
  __syncthreads();
  if(tid < 64){
    int tok = stok;
    g_xgruT[tid*BB + b] = emb[(size_t)tok*EE + tid];
  }
}

// ---------------- launch ----------------
extern "C" void kernel_launch(void* const* d_in, const int* in_sizes, int n_in,
                              void* d_out, int out_size) {
  const int*   seq     = (const int*)  d_in[0];
  const float* emb     = (const float*)d_in[2];
  const float* encWih  = (const float*)d_in[3];
  const float* encWhh  = (const float*)d_in[4];
  const float* encbih  = (const float*)d_in[5];
  const float* encbhh  = (const float*)d_in[6];
  const float* attnW   = (const float*)d_in[7];
  const float* attnb   = (const float*)d_in[8];
  const float* attnv   = (const float*)d_in[9];
  const float* dWih    = (const float*)d_in[10];
  const float* dWhh    = (const float*)d_in[11];
  const float* dbih    = (const float*)d_in[12];
  const float* dbhh    = (const float*)d_in[13];
  const float* outW    = (const float*)d_in[14];
  const float* outb    = (const float*)d_in[15];
  float* out = (float*)d_out;

  const int ENC_SMEM = (12288 + 128 + 384 + 384) * 4;   // 52736 B
  cudaFuncSetAttribute(k_encrec, cudaFuncAttributeMaxDynamicSharedMemorySize, ENC_SMEM);
  cudaFuncSetAttribute(k_logits, cudaFuncAttributeMaxDynamicSharedMemorySize, LOG_SMEM);

  // setup
  k_transp<<<dim3(VV/32, 8), dim3(32,8)>>>(outW);
  k_giall<<<512, 384>>>(seq, emb, encWih, encbih);
  k_emb0<<<64, 128>>>(seq, emb);
  k_encrec<<<128, 384, ENC_SMEM>>>(encWhh, encbhh);
  k_encproj<<<512, 256>>>(attnW, attnb);

  // decode
  for(int t=0; t<TT; t++){
    k_att<<<128, 256>>>(attnW, attnv);
    k_dgates<<<96, 128>>>(dWih, dWhh, dbih, dbhh);
    k_dcombine<<<128, 128>>>();
    k_logits<<<148, 256, LOG_SMEM>>>(outb, out, t);
    k_argmax<<<128, 256>>>(out, emb, t);
  }
}

// round 6
// speedup vs baseline: 1.2194x; 1.2194x over previous
#include <cuda_runtime.h>
#include <cuda_bf16.h>
#include <math.h>
#include <stdint.h>

#define VV 32000
#define EE 64
#define HH 128
#define SS 1024
#define BB 128
#define TT 64
#define GG 384
#define NT 64
#define NTILES 500        // VV / NT

// ---------------- device scratch ----------------
__device__ float g_gi[(size_t)SS*BB*GG];
__device__ float g_enc_out[(size_t)SS*BB*HH];    // [s][b][h]
__device__ float g_enc_proj[(size_t)SS*BB*HH];   // [s][b][h]
__device__ float g_enc_projT[(size_t)BB*HH*SS];  // [b][h][s]
__device__ __nv_bfloat16 g_Wh[(size_t)VV*256];
__device__ __nv_bfloat16 g_Wm[(size_t)VV*256];
__device__ __nv_bfloat16 g_Wl[(size_t)VV*256];
__device__ float g_h[BB*HH];
__device__ float g_hT[HH*BB];
__device__ float g_xgruT[192*BB];
__device__ float g_xlog[BB*256];                 // [b][k]: h2(0..127), ctx(128..255)
__device__ float g_gdi[GG*BB];
__device__ float g_gdh[GG*BB];
__device__ float g_pval[BB*512];
__device__ int   g_pidx[BB*512];

__device__ __forceinline__ float sig_acc(float x){ return 1.0f/(1.0f + expf(-x)); }
__device__ __forceinline__ float tanh_fast(float x){
  return 1.0f - __fdividef(2.0f, __expf(2.0f*x) + 1.0f);
}

// ---------------- helpers ----------------
__device__ __forceinline__ uint32_t s2u(const void* p){
  uint32_t a;
  asm("{ .reg .u64 t; cvta.to.shared.u64 t, %1; cvt.u32.u64 %0, t; }" : "=r"(a) : "l"(p));
  return a;
}
__device__ __forceinline__ void sts128(uint32_t addr, uint4 v){
  asm volatile("st.shared.v4.b32 [%0], {%1,%2,%3,%4};" :: "r"(addr), "r"(v.x), "r"(v.y), "r"(v.z), "r"(v.w) : "memory");
}
__device__ __forceinline__ uint32_t lds32(uint32_t addr){
  uint32_t v; asm volatile("ld.shared.b32 %0, [%1];" : "=r"(v) : "r"(addr)); return v;
}
__device__ __forceinline__ uint32_t pack_bf2(__nv_bfloat16 lo, __nv_bfloat16 hi){
  return ((uint32_t)__bfloat16_as_ushort(hi)<<16) | (uint32_t)__bfloat16_as_ushort(lo);
}
__device__ __forceinline__ void split3(float2 f, uint32_t& h, uint32_t& m, uint32_t& l){
  __nv_bfloat16 h0=__float2bfloat16(f.x), h1=__float2bfloat16(f.y);
  float r0=f.x-__bfloat162float(h0), r1=f.y-__bfloat162float(h1);
  __nv_bfloat16 m0=__float2bfloat16(r0), m1=__float2bfloat16(r1);
  r0-=__bfloat162float(m0); r1-=__bfloat162float(m1);
  h=pack_bf2(h0,h1); m=pack_bf2(m0,m1);
  l=pack_bf2(__float2bfloat16(r0),__float2bfloat16(r1));
}

#define MMA(cc, aa, bb0, bb1) \
  asm volatile("mma.sync.aligned.m16n8k16.row.col.f32.bf16.bf16.f32 " \
    "{%0,%1,%2,%3}, {%4,%5,%6,%7}, {%8,%9}, {%0,%1,%2,%3};" \
    : "+f"(cc[0]),"+f"(cc[1]),"+f"(cc[2]),"+f"(cc[3]) \
    : "r"(aa[0]),"r"(aa[1]),"r"(aa[2]),"r"(aa[3]), "r"(bb0),"r"(bb1))

// ---------------- setup: split out_W into 3 bf16 levels ----------------
__global__ void k_wsplit(const float* __restrict__ outW){
  size_t i4 = (size_t)blockIdx.x*256 + threadIdx.x;  // float4 index, 2,048,000 total
  float4 w = ((const float4*)outW)[i4];
  uint2 uh, um, ul;
  float2 p0 = make_float2(w.x, w.y), p1 = make_float2(w.z, w.w);
  split3(p0, uh.x, um.x, ul.x);
  split3(p1, uh.y, um.y, ul.y);
  ((uint2*)g_Wh)[i4] = uh;
  ((uint2*)g_Wm)[i4] = um;
  ((uint2*)g_Wl)[i4] = ul;
}

// ---------------- setup: first decoder token embedding ----------------
__global__ void k_emb0(const int* __restrict__ seq, const float* __restrict__ emb){
  int k = blockIdx.x, b = threadIdx.x;
  int tok = seq[b];
  g_xgruT[k*BB + b] = emb[(size_t)tok*EE + k];
}

// ---------------- encoder input projection ----------------
__global__ void __launch_bounds__(384,2) k_giall(const int* __restrict__ seq,
      const float* __restrict__ emb, const float* __restrict__ Wih,
      const float* __restrict__ bih){
  int g = threadIdx.x;
  float w[64];
  const float4* wp = (const float4*)(Wih + (size_t)g*64);
  #pragma unroll
  for(int i=0;i<16;i++){ float4 q=wp[i]; w[4*i]=q.x; w[4*i+1]=q.y; w[4*i+2]=q.z; w[4*i+3]=q.w; }
  float bias = bih[g];
  __shared__ float xs[2][64];
  const int ROWS = (SS*BB)/512;   // 256
  size_t base = (size_t)blockIdx.x * ROWS;
  if(g<64){ int tok0 = seq[base]; xs[0][g] = emb[(size_t)tok0*EE + g]; }
  __syncthreads();
  for(int r=0;r<ROWS;r++){
    int cur=r&1, nxt=cur^1;
    if(r+1<ROWS && g<64){
      int tok2 = seq[base+r+1];
      xs[nxt][g] = emb[(size_t)tok2*EE + g];
    }
    float a0=0,a1=0,a2=0,a3=0;
    #pragma unroll
    for(int k=0;k<64;k+=4){
      a0 += w[k]*xs[cur][k];     a1 += w[k+1]*xs[cur][k+1];
      a2 += w[k+2]*xs[cur][k+2]; a3 += w[k+3]*xs[cur][k+3];
    }
    g_gi[(base+r)*GG + g] = (a0+a1)+(a2+a3) + bias;
    __syncthreads();
  }
}

// ---------------- encoder recurrence ----------------
__global__ void __launch_bounds__(384,1) k_encrec(const float* __restrict__ Whh,
      const float* __restrict__ bhh){
  extern __shared__ float sm[];
  float* whh_s = sm;
  float* hs    = sm + 12288;
  float* ghs   = hs + 128;
  float* gis   = ghs + 384;
  int b = blockIdx.x;
  int g = threadIdx.x;
  float w[96];
  {
    const float4* wlo = (const float4*)(Whh + (size_t)g*128);
    #pragma unroll
    for(int i=0;i<24;i++){ float4 q=wlo[i]; w[4*i]=q.x; w[4*i+1]=q.y; w[4*i+2]=q.z; w[4*i+3]=q.w; }
    const float4* whi = (const float4*)(Whh + (size_t)g*128 + 96);
    #pragma unroll
    for(int i=0;i<8;i++) ((float4*)whh_s)[i*384 + g] = whi[i];
  }
  float bias = bhh[g];
  if(g<128) hs[g] = 0.0f;
  __syncthreads();

  float giv = g_gi[(size_t)b*GG + g];
  for(int s=0;s<SS;s++){
    float gi_next = 0.0f;
    if(s+1<SS) gi_next = g_gi[((size_t)(s+1)*BB + b)*GG + g];
    gis[g] = giv;
    float a0=0,a1=0,a2=0,a3=0;
    #pragma unroll
    for(int i=0;i<24;i++){
      float4 hv = ((float4*)hs)[i];
      a0 += w[4*i]*hv.x;   a1 += w[4*i+1]*hv.y;
      a2 += w[4*i+2]*hv.z; a3 += w[4*i+3]*hv.w;
    }
    #pragma unroll
    for(int i=0;i<8;i++){
      float4 wv = ((float4*)whh_s)[i*384 + g];
      float4 hv = ((float4*)hs)[24 + i];
      a0 += wv.x*hv.x; a1 += wv.y*hv.y; a2 += wv.z*hv.z; a3 += wv.w*hv.w;
    }
    ghs[g] = (a0+a1)+(a2+a3) + bias;
    __syncthreads();
    if(g<128){
      float rr = sig_acc(gis[g]       + ghs[g]);
      float zz = sig_acc(gis[128+g]   + ghs[128+g]);
      float nn = tanhf (gis[256+g] + rr*ghs[256+g]);
      float hn = (1.0f-zz)*nn + zz*hs[g];
      g_enc_out[((size_t)s*BB + b)*HH + g] = hn;
      hs[g] = hn;
    }
    __syncthreads();
    giv = gi_next;
  }
  if(g<128){
    g_h[b*HH + g]  = hs[g];
    g_hT[g*BB + b] = hs[g];
  }
}

// ---------------- enc_proj = enc_out @ attn_W[:,128:].T + attn_b ----------------
__global__ void __launch_bounds__(256,2) k_encproj(const float* __restrict__ attnW,
                                                   const float* __restrict__ attnb){
  int t = threadIdx.x;
  int j = t & 127, half = t >> 7;
  float w[64];
  const float4* wp = (const float4*)(attnW + (size_t)j*256 + 128 + half*64);
  #pragma unroll
  for(int i=0;i<16;i++){ float4 q=wp[i]; w[4*i]=q.x; w[4*i+1]=q.y; w[4*i+2]=q.z; w[4*i+3]=q.w; }
  float bias = attnb[j];
  __shared__ float xs[2][128];
  __shared__ float part[2][128];
  const int ROWS = (SS*BB)/512;
  size_t base = (size_t)blockIdx.x * ROWS;
  if(t<128) xs[0][t] = g_enc_out[base*HH + t];
  __syncthreads();
  for(int r=0;r<ROWS;r++){
    int cur=r&1, nxt=cur^1;
    if(r+1<ROWS && t<128) xs[nxt][t] = g_enc_out[(base+r+1)*HH + t];
    float a0=0,a1=0,a2=0,a3=0;
    const float* xp = &xs[cur][half*64];
    #pragma unroll
    for(int k=0;k<64;k+=4){
      a0+=w[k]*xp[k]; a1+=w[k+1]*xp[k+1]; a2+=w[k+2]*xp[k+2]; a3+=w[k+3]*xp[k+3];
    }
    part[half][j] = (a0+a1)+(a2+a3);
    __syncthreads();
    if(!half) g_enc_proj[(base+r)*HH + j] = part[0][j] + part[1][j] + bias;
    __syncthreads();
  }
}

// ---------------- transpose enc_proj [S][B*H] -> enc_projT [B*H][S] ----------------
__global__ void k_transposeP(){
  __shared__ float tile[32][33];
  int s0 = blockIdx.x*32;
  int c0 = blockIdx.y*32;
  int tx = threadIdx.x, ty = threadIdx.y;
  #pragma unroll
  for(int i=0;i<32;i+=8)
    tile[ty+i][tx] = g_enc_proj[(size_t)(s0+ty+i)*(BB*HH) + c0+tx];
  __syncthreads();
  #pragma unroll
  for(int i=0;i<32;i+=8)
    g_enc_projT[(size_t)(c0+ty+i)*SS + s0+tx] = tile[tx][ty+i];
}

// ---------------- decoder: fused hp + scores + softmax + context ----------------
__global__ void __launch_bounds__(256,1) k_att(const float* __restrict__ attnW,
                                               const float* __restrict__ attnv){
  __shared__ float hs[128], hp[128], part[128], vsd[128];
  __shared__ float ws[1024];
  __shared__ float red[40];
  __shared__ float4 cbuf[8][32];
  int b = blockIdx.x, t = threadIdx.x;
  int lane = t&31, warp = t>>5;
  if(t<128){ hs[t] = g_h[b*HH + t]; vsd[t] = attnv[t]; }
  __syncthreads();
  // hp = h @ attn_W[:, :128].T
  {
    int j = t & 127, half = t >> 7;
    const float4* wr = (const float4*)(attnW + (size_t)j*256 + half*64);
    const float* hb = &hs[half*64];
    float a = 0.0f;
    #pragma unroll
    for(int i=0;i<16;i++){
      float4 q = wr[i];
      a += q.x*hb[4*i] + q.y*hb[4*i+1] + q.z*hb[4*i+2] + q.w*hb[4*i+3];
    }
    if(half) part[j] = a;
    __syncthreads();
    if(!half) hp[j] = a + part[j];
    __syncthreads();
  }
  // scores: coalesced transposed reads, 4 s per thread
  {
    const float* base = g_enc_projT + (size_t)b*HH*SS;
    float a0=0,a1=0,a2=0,a3=0;
    #pragma unroll 2
    for(int h=0;h<128;h++){
      float hpv = hp[h], vv = vsd[h];
      const float* p = base + (size_t)h*SS + t;
      float e0 = p[0], e1 = p[256], e2 = p[512], e3 = p[768];
      a0 += tanh_fast(e0+hpv)*vv;
      a1 += tanh_fast(e1+hpv)*vv;
      a2 += tanh_fast(e2+hpv)*vv;
      a3 += tanh_fast(e3+hpv)*vv;
    }
    ws[t]=a0; ws[t+256]=a1; ws[t+512]=a2; ws[t+768]=a3;
  }
  __syncthreads();
  // softmax
  {
    float4 sc = ((float4*)ws)[t];
    float m = fmaxf(fmaxf(sc.x,sc.y), fmaxf(sc.z,sc.w));
    #pragma unroll
    for(int o=16;o;o>>=1) m = fmaxf(m, __shfl_xor_sync(0xffffffffu,m,o));
    if(lane==0) red[warp] = m;
    __syncthreads();
    if(t==0){ float mm=red[0]; for(int i=1;i<8;i++) mm=fmaxf(mm,red[i]); red[8]=mm; }
    __syncthreads();
    float M = red[8];
    float4 e;
    e.x=expf(sc.x-M); e.y=expf(sc.y-M); e.z=expf(sc.z-M); e.w=expf(sc.w-M);
    ((float4*)ws)[t] = e;
    float ssum = (e.x+e.y)+(e.z+e.w);
    #pragma unroll
    for(int o=16;o;o>>=1) ssum += __shfl_xor_sync(0xffffffffu, ssum, o);
    if(lane==0) red[16+warp] = ssum;
    __syncthreads();
    if(t==0){ float s2=0; for(int i=0;i<8;i++) s2+=red[16+i]; red[24]=s2; }
    __syncthreads();
  }
  float inv = 1.0f / red[24];
  // context
  {
    int hq = t&31, sg = t>>5;
    float4 acc = make_float4(0,0,0,0);
    #pragma unroll 4
    for(int i=0;i<128;i++){
      int s = sg + (i<<3);
      float wg = ws[s];
      float4 ev = ((const float4*)(g_enc_out + ((size_t)s*BB + b)*HH))[hq];
      acc.x += wg*ev.x; acc.y += wg*ev.y; acc.z += wg*ev.z; acc.w += wg*ev.w;
    }
    cbuf[sg][hq] = acc;
    __syncthreads();
    if(t<32){
      float4 tot = cbuf[0][t];
      #pragma unroll
      for(int g2=1;g2<8;g2++){
        float4 c = cbuf[g2][t];
        tot.x+=c.x; tot.y+=c.y; tot.z+=c.z; tot.w+=c.w;
      }
      tot.x*=inv; tot.y*=inv; tot.z*=inv; tot.w*=inv;
      int h0 = t*4;
      float vals[4] = {tot.x, tot.y, tot.z, tot.w};
      #pragma unroll
      for(int jj=0;jj<4;jj++){
        float val = vals[jj];
        g_xgruT[(64 + h0+jj)*BB + b] = val;
        g_xlog[b*256 + 128 + h0+jj]  = val;
      }
    }
  }
}

// ---------------- decoder GRU gate GEMVs ----------------
__global__ void __launch_bounds__(128,4) k_dgates(const float* __restrict__ dWih,
      const float* __restrict__ dWhh, const float* __restrict__ dbih,
      const float* __restrict__ dbhh){
  __shared__ float wi[4][192], wh[4][128];
  int b = threadIdx.x;
  int g0 = blockIdx.x*4;
  for(int i=threadIdx.x; i<4*192; i+=128) wi[i/192][i%192] = dWih[(size_t)(g0 + i/192)*192 + (i%192)];
  for(int i=threadIdx.x; i<4*128; i+=128) wh[i/128][i%128] = dWhh[(size_t)(g0 + i/128)*128 + (i%128)];
  __syncthreads();
  float ai0=dbih[g0], ai1=dbih[g0+1], ai2=dbih[g0+2], ai3=dbih[g0+3];
  float ah0=dbhh[g0], ah1=dbhh[g0+1], ah2=dbhh[g0+2], ah3=dbhh[g0+3];
  #pragma unroll 4
  for(int k=0;k<192;k++){
    float xv = g_xgruT[k*BB + b];
    ai0 += wi[0][k]*xv; ai1 += wi[1][k]*xv; ai2 += wi[2][k]*xv; ai3 += wi[3][k]*xv;
  }
  #pragma unroll 4
  for(int k=0;k<128;k++){
    float hv = g_hT[k*BB + b];
    ah0 += wh[0][k]*hv; ah1 += wh[1][k]*hv; ah2 += wh[2][k]*hv; ah3 += wh[3][k]*hv;
  }
  g_gdi[(g0+0)*BB+b]=ai0; g_gdi[(g0+1)*BB+b]=ai1; g_gdi[(g0+2)*BB+b]=ai2; g_gdi[(g0+3)*BB+b]=ai3;
  g_gdh[(g0+0)*BB+b]=ah0; g_gdh[(g0+1)*BB+b]=ah1; g_gdh[(g0+2)*BB+b]=ah2; g_gdh[(g0+3)*BB+b]=ah3;
}

// ---------------- decoder GRU combine ----------------
__global__ void __launch_bounds__(128,8) k_dcombine(){
  int b = blockIdx.x, h = threadIdx.x;
  float ir = g_gdi[h*BB+b],  iz = g_gdi[(128+h)*BB+b], in_ = g_gdi[(256+h)*BB+b];
  float hr = g_gdh[h*BB+b],  hz = g_gdh[(128+h)*BB+b], hn  = g_gdh[(256+h)*BB+b];
  float rr = sig_acc(ir+hr), zz = sig_acc(iz+hz);
  float nn = tanhf(in_ + rr*hn);
  float hold = g_h[b*HH + h];
  float hnew = (1.0f-zz)*nn + zz*hold;
  g_h[b*HH + h]     = hnew;
  g_hT[h*BB + b]    = hnew;
  g_xlog[b*256 + h] = hnew;
}

// ---------------- logits GEMM: mma.sync bf16 3-way split + fused argmax ----------------
// B smem rows: stride 264 bf16 = 528B -> conflict-free b-frag loads
#define BSTRIDE_B 528
#define SPLIT_BYTES (64*BSTRIDE_B)         // 33792
#define LOG_DYN (3*SPLIT_BYTES + 256)      // 101632
__global__ void __launch_bounds__(256,1) k_logits(const float* __restrict__ outb,
                                                  float* __restrict__ out, int t){
  extern __shared__ char dyn[];
  uint32_t sb = s2u(dyn);
  uint32_t bhA = sb, bmA = sb + SPLIT_BYTES, blA = sb + 2*SPLIT_BYTES;
  float* sbias = (float*)(dyn + 3*SPLIT_BYTES);
  int tid = threadIdx.x;
  int wid = tid>>5, lane = tid&31;
  int r = lane>>2, tig = lane&3;
  int b0 = wid*16 + r, b1 = b0 + 8;
  const float* x0p = g_xlog + b0*256;
  const float* x1p = g_xlog + b1*256;
  float* outRow = out + (size_t)t*BB*VV;

  for(int tile = blockIdx.x; tile < NTILES; tile += 148){
    int v0 = tile*NT;
    __syncthreads();
    // load B splits to smem
    {
      const uint4* srcH = (const uint4*)(g_Wh + (size_t)v0*256);
      const uint4* srcM = (const uint4*)(g_Wm + (size_t)v0*256);
      const uint4* srcL = (const uint4*)(g_Wl + (size_t)v0*256);
      #pragma unroll
      for(int j=0;j<8;j++){
        int idx = tid + j*256;            // 0..2047 uint4s
        int row = idx>>5, c = idx&31;
        uint32_t off = (uint32_t)row*BSTRIDE_B + (uint32_t)c*16u;
        sts128(bhA + off, srcH[idx]);
        sts128(bmA + off, srcM[idx]);
        sts128(blA + off, srcL[idx]);
      }
      if(tid<64) sbias[tid] = outb[v0+tid];
    }
    __syncthreads();

    float c[8][4];
    #pragma unroll
    for(int i=0;i<8;i++){ c[i][0]=0.f;c[i][1]=0.f;c[i][2]=0.f;c[i][3]=0.f; }

    #pragma unroll
    for(int kc=0;kc<2;kc++){
      // build A fragments (split fp32 -> 3x bf16)
      uint32_t ah[8][4], am[8][4], al[8][4];
      #pragma unroll
      for(int ks=0;ks<8;ks++){
        int kk = kc*128 + ks*16 + tig*2;
        float2 f0 = *(const float2*)(x0p + kk);
        float2 f1 = *(const float2*)(x1p + kk);
        float2 f2 = *(const float2*)(x0p + kk + 8);
        float2 f3 = *(const float2*)(x1p + kk + 8);
        split3(f0, ah[ks][0], am[ks][0], al[ks][0]);
        split3(f1, ah[ks][1], am[ks][1], al[ks][1]);
        split3(f2, ah[ks][2], am[ks][2], al[ks][2]);
        split3(f3, ah[ks][3], am[ks][3], al[ks][3]);
      }
      #pragma unroll
      for(int ks=0;ks<8;ks++){
        uint32_t kb = (uint32_t)(kc*128 + ks*16 + tig*2)*2u;  // byte offset within row
        #pragma unroll
        for(int ns=0;ns<8;ns++){
          uint32_t roff = (uint32_t)(ns*8 + r)*BSTRIDE_B + kb;
          uint32_t bh0 = lds32(bhA + roff), bh1 = lds32(bhA + roff + 16);
          uint32_t bm0 = lds32(bmA + roff), bm1 = lds32(bmA + roff + 16);
          uint32_t bl0 = lds32(blA + roff), bl1 = lds32(blA + roff + 16);
          MMA(c[ns], ah[ks], bh0, bh1);
          MMA(c[ns], ah[ks], bm0, bm1);
          MMA(c[ns], ah[ks], bl0, bl1);
          MMA(c[ns], am[ks], bh0, bh1);
          MMA(c[ns], am[ks], bm0, bm1);
          MMA(c[ns], al[ks], bh0, bh1);
        }
      }
    }
    // epilogue: bias + store + per-row argmax partial
    float bv0=-3.4e38f, bv1=-3.4e38f; int bi0=0x7fffffff, bi1=0x7fffffff;
    #pragma unroll
    for(int ns=0;ns<8;ns++){
      int n = ns*8 + tig*2;
      float f0 = c[ns][0] + sbias[n];
      float f1 = c[ns][1] + sbias[n+1];
      float f2 = c[ns][2] + sbias[n];
      float f3 = c[ns][3] + sbias[n+1];
      if(f0>bv0){bv0=f0;bi0=v0+n;}
      if(f1>bv0){bv0=f1;bi0=v0+n+1;}
      if(f2>bv1){bv1=f2;bi1=v0+n;}
      if(f3>bv1){bv1=f3;bi1=v0+n+1;}
      *(float2*)(outRow + (size_t)b0*VV + v0 + n) = make_float2(f0,f1);
      *(float2*)(outRow + (size_t)b1*VV + v0 + n) = make_float2(f2,f3);
    }
    #pragma unroll
    for(int o=1;o<4;o<<=1){
      float ov0=__shfl_xor_sync(0xffffffffu,bv0,o); int oi0=__shfl_xor_sync(0xffffffffu,bi0,o);
      float ov1=__shfl_xor_sync(0xffffffffu,bv1,o); int oi1=__shfl_xor_sync(0xffffffffu,bi1,o);
      if(ov0>bv0||(ov0==bv0&&oi0<bi0)){bv0=ov0;bi0=oi0;}
      if(ov1>bv1||(ov1==bv1&&oi1<bi1)){bv1=ov1;bi1=oi1;}
    }
    if(tig==0){
      g_pval[b0*512 + tile]=bv0; g_pidx[b0*512 + tile]=bi0;
      g_pval[b1*512 + tile]=bv1; g_pidx[b1*512 + tile]=bi1;
    }
  }
}

// ---------------- argmax merge + feedback embedding ----------------
__global__ void __launch_bounds__(256,1) k_amerge(const float* __restrict__ emb){
  __shared__ float sv[8];
  __shared__ int   si[8];
  __shared__ int   stok;
  int b = blockIdx.x, tid = threadIdx.x;
  int lane = tid&31, w = tid>>5;
  float v = -3.4e38f; int ix = 0x7fffffff;
  if(tid < NTILES){ v = g_pval[b*512 + tid]; ix = g_pidx[b*512 + tid]; }
  int t2 = tid + 256;
  if(t2 < NTILES){
    float v2 = g_pval[b*512 + t2]; int i2 = g_pidx[b*512 + t2];
    if(v2 > v || (v2 == v && i2 < ix)){ v = v2; ix = i2; }
  }
  #pragma unroll
  for(int o=16;o;o>>=1){
    float ov = __shfl_xor_sync(0xffffffffu, v, o);
    int   oi = __shfl_xor_sync(0xffffffffu, ix, o);
    if(ov > v || (ov == v && oi < ix)){ v = ov; ix = oi; }
  }
  if(lane==0){ sv[w]=v; si[w]=ix; }
  __syncthreads();
  if(tid==0){
    float bv = sv[0]; int bx = si[0];
    for(int i=1;i<8;i++){
      if(sv[i] > bv || (sv[i]==bv && si[i]<bx)){ bv=sv[i]; bx=si[i]; }
    }
    stok = bx;
  }
  __syncthreads();
  if(tid < 64){
    int tok = stok;
    g_xgruT[tid*BB + b] = emb[(size_t)tok*EE + tid];
  }
}

// ---------------- launch ----------------
extern "C" void kernel_launch(void* const* d_in, const int* in_sizes, int n_in,
                              void* d_out, int out_size) {
  const int*   seq     = (const int*)  d_in[0];
  const float* emb     = (const float*)d_in[2];
  const float* encWih  = (const float*)d_in[3];
  const float* encWhh  = (const float*)d_in[4];
  const float* encbih  = (const float*)d_in[5];
  const float* encbhh  = (const float*)d_in[6];
  const float* attnW   = (const float*)d_in[7];
  const float* attnb   = (const float*)d_in[8];
  const float* attnv   = (const float*)d_in[9];
  const float* dWih    = (const float*)d_in[10];
  const float* dWhh    = (const float*)d_in[11];
  const float* dbih    = (const float*)d_in[12];
  const float* dbhh    = (const float*)d_in[13];
  const float* outW    = (const float*)d_in[14];
  const float* outb    = (const float*)d_in[15];
  float* out = (float*)d_out;

  const int ENC_SMEM = (12288 + 128 + 384 + 384) * 4;
  cudaFuncSetAttribute(k_encrec, cudaFuncAttributeMaxDynamicSharedMemorySize, ENC_SMEM);
  cudaFuncSetAttribute(k_logits, cudaFuncAttributeMaxDynamicSharedMemorySize, LOG_DYN);

  // setup
  k_wsplit<<<8000, 256>>>(outW);
  k_giall<<<512, 384>>>(seq, emb, encWih, encbih);
  k_emb0<<<64, 128>>>(seq, emb);
  k_encrec<<<128, 384, ENC_SMEM>>>(encWhh, encbhh);
  k_encproj<<<512, 256>>>(attnW, attnb);
  k_transposeP<<<dim3(32,512), dim3(32,8)>>>();

  // decode
  for(int t=0; t<TT; t++){
    k_att<<<128, 256>>>(attnW, attnv);
    k_dgates<<<96, 128>>>(dWih, dWhh, dbih, dbhh);
    k_dcombine<<<128, 128>>>();
    k_logits<<<148, 256, LOG_DYN>>>(outb, out, t);
    k_amerge<<<128, 256>>>(emb);
  }
}

// round 7
// speedup vs baseline: 1.4593x; 1.1967x over previous
#include <cuda_runtime.h>
#include <cuda_bf16.h>
#include <math.h>
#include <stdint.h>

#define VV 32000
#define EE 64
#define HH 128
#define SS 1024
#define BB 128
#define TT 64
#define GG 384
#define NT 64
#define NTILES 500        // VV / NT

// ---------------- device scratch ----------------
__device__ float g_gi[(size_t)SS*BB*GG];
__device__ float g_eoT[(size_t)BB*SS*HH];     // enc_out [b][s][h]
__device__ float g_epBS[(size_t)BB*SS*HH];    // enc_proj [b][s][h]
__device__ float g_epT[(size_t)BB*HH*SS];     // enc_proj [b][h][s]
__device__ __nv_bfloat16 g_Wh[(size_t)VV*256];
__device__ __nv_bfloat16 g_Wm[(size_t)VV*256];
__device__ __nv_bfloat16 g_Wl[(size_t)VV*256];
__device__ float2 g_wiT2[192*192];            // [k][jpair] of dec_Wih
__device__ float2 g_whT2[128*192];            // [k][jpair] of dec_Whh
__device__ float g_h[BB*HH];
__device__ uint32_t g_xh[BB*128];             // xlog bf16x2 splits [b][pair]
__device__ uint32_t g_xm[BB*128];
__device__ uint32_t g_xl[BB*128];
__device__ float g_pval[BB*512];
__device__ int   g_pidx[BB*512];

__device__ __forceinline__ float sig_acc(float x){ return 1.0f/(1.0f + expf(-x)); }
__device__ __forceinline__ float tanh_fast(float x){
  return 1.0f - __fdividef(2.0f, __expf(2.0f*x) + 1.0f);
}

// ---------------- helpers ----------------
__device__ __forceinline__ uint32_t s2u(const void* p){
  uint32_t a;
  asm("{ .reg .u64 t; cvta.to.shared.u64 t, %1; cvt.u32.u64 %0, t; }" : "=r"(a) : "l"(p));
  return a;
}
__device__ __forceinline__ uint32_t pack_bf2(__nv_bfloat16 lo, __nv_bfloat16 hi){
  return ((uint32_t)__bfloat16_as_ushort(hi)<<16) | (uint32_t)__bfloat16_as_ushort(lo);
}
__device__ __forceinline__ void split3(float2 f, uint32_t& h, uint32_t& m, uint32_t& l){
  __nv_bfloat16 h0=__float2bfloat16(f.x), h1=__float2bfloat16(f.y);
  float r0=f.x-__bfloat162float(h0), r1=f.y-__bfloat162float(h1);
  __nv_bfloat16 m0=__float2bfloat16(r0), m1=__float2bfloat16(r1);
  r0-=__bfloat162float(m0); r1-=__bfloat162float(m1);
  h=pack_bf2(h0,h1); m=pack_bf2(m0,m1);
  l=pack_bf2(__float2bfloat16(r0),__float2bfloat16(r1));
}
__device__ __forceinline__ void cpasync16(uint32_t saddr, const void* gaddr){
  asm volatile("cp.async.cg.shared.global [%0], [%1], 16;" :: "r"(saddr), "l"(gaddr) : "memory");
}

#define MMA(cc, aa, bb0, bb1) \
  asm volatile("mma.sync.aligned.m16n8k16.row.col.f32.bf16.bf16.f32 " \
    "{%0,%1,%2,%3}, {%4,%5,%6,%7}, {%8,%9}, {%0,%1,%2,%3};" \
    : "+f"(cc[0]),"+f"(cc[1]),"+f"(cc[2]),"+f"(cc[3]) \
    : "r"(aa[0]),"r"(aa[1]),"r"(aa[2]),"r"(aa[3]), "r"(bb0),"r"(bb1))

#define LDSM4(r0,r1,r2,r3,addr) \
  asm volatile("ldmatrix.sync.aligned.m8n8.x4.shared.b16 {%0,%1,%2,%3}, [%4];" \
    : "=r"(r0),"=r"(r1),"=r"(r2),"=r"(r3) : "r"(addr))

// ---------------- setup: split out_W into 3 bf16 levels ----------------
__global__ void k_wsplit(const float* __restrict__ outW){
  size_t i4 = (size_t)blockIdx.x*256 + threadIdx.x;
  float4 w = ((const float4*)outW)[i4];
  uint2 uh, um, ul;
  float2 p0 = make_float2(w.x, w.y), p1 = make_float2(w.z, w.w);
  split3(p0, uh.x, um.x, ul.x);
  split3(p1, uh.y, um.y, ul.y);
  ((uint2*)g_Wh)[i4] = uh;
  ((uint2*)g_Wm)[i4] = um;
  ((uint2*)g_Wl)[i4] = ul;
}

// ---------------- setup: transpose decoder GRU weights into [k][jpair] ----------------
__global__ void k_wtrans(const float* __restrict__ dWih, const float* __restrict__ dWhh){
  int idx = blockIdx.x*256 + threadIdx.x;
  if(idx < 192*192){
    int k = idx/192, j = idx%192;
    g_wiT2[idx] = make_float2(dWih[(size_t)(2*j)*192+k], dWih[(size_t)(2*j+1)*192+k]);
  } else {
    int i2 = idx - 192*192;
    if(i2 < 128*192){
      int k = i2/192, j = i2%192;
      g_whT2[i2] = make_float2(dWhh[(size_t)(2*j)*128+k], dWhh[(size_t)(2*j+1)*128+k]);
    }
  }
}

// ---------------- encoder input projection ----------------
__global__ void __launch_bounds__(384,2) k_giall(const int* __restrict__ seq,
      const float* __restrict__ emb, const float* __restrict__ Wih,
      const float* __restrict__ bih){
  int g = threadIdx.x;
  float w[64];
  const float4* wp = (const float4*)(Wih + (size_t)g*64);
  #pragma unroll
  for(int i=0;i<16;i++){ float4 q=wp[i]; w[4*i]=q.x; w[4*i+1]=q.y; w[4*i+2]=q.z; w[4*i+3]=q.w; }
  float bias = bih[g];
  __shared__ float xs[2][64];
  const int ROWS = (SS*BB)/512;   // 256
  size_t base = (size_t)blockIdx.x * ROWS;
  if(g<64){ int tok0 = seq[base]; xs[0][g] = emb[(size_t)tok0*EE + g]; }
  __syncthreads();
  for(int r=0;r<ROWS;r++){
    int cur=r&1, nxt=cur^1;
    if(r+1<ROWS && g<64){
      int tok2 = seq[base+r+1];
      xs[nxt][g] = emb[(size_t)tok2*EE + g];
    }
    float a0=0,a1=0,a2=0,a3=0;
    #pragma unroll
    for(int k=0;k<64;k+=4){
      a0 += w[k]*xs[cur][k];     a1 += w[k+1]*xs[cur][k+1];
      a2 += w[k+2]*xs[cur][k+2]; a3 += w[k+3]*xs[cur][k+3];
    }
    g_gi[(base+r)*GG + g] = (a0+a1)+(a2+a3) + bias;
    __syncthreads();
  }
}

// ---------------- encoder recurrence (writes enc_out transposed [b][s][h]) ----------------
__global__ void __launch_bounds__(384,1) k_encrec(const float* __restrict__ Whh,
      const float* __restrict__ bhh){
  extern __shared__ float sm[];
  float* whh_s = sm;
  float* hs    = sm + 12288;
  float* ghs   = hs + 128;
  float* gis   = ghs + 384;
  int b = blockIdx.x;
  int g = threadIdx.x;
  float w[96];
  {
    const float4* wlo = (const float4*)(Whh + (size_t)g*128);
    #pragma unroll
    for(int i=0;i<24;i++){ float4 q=wlo[i]; w[4*i]=q.x; w[4*i+1]=q.y; w[4*i+2]=q.z; w[4*i+3]=q.w; }
    const float4* whi = (const float4*)(Whh + (size_t)g*128 + 96);
    #pragma unroll
    for(int i=0;i<8;i++) ((float4*)whh_s)[i*384 + g] = whi[i];
  }
  float bias = bhh[g];
  if(g<128) hs[g] = 0.0f;
  __syncthreads();

  float giv = g_gi[(size_t)b*GG + g];
  for(int s=0;s<SS;s++){
    float gi_next = 0.0f;
    if(s+1<SS) gi_next = g_gi[((size_t)(s+1)*BB + b)*GG + g];
    gis[g] = giv;
    float a0=0,a1=0,a2=0,a3=0;
    #pragma unroll
    for(int i=0;i<24;i++){
      float4 hv = ((float4*)hs)[i];
      a0 += w[4*i]*hv.x;   a1 += w[4*i+1]*hv.y;
      a2 += w[4*i+2]*hv.z; a3 += w[4*i+3]*hv.w;
    }
    #pragma unroll
    for(int i=0;i<8;i++){
      float4 wv = ((float4*)whh_s)[i*384 + g];
      float4 hv = ((float4*)hs)[24 + i];
      a0 += wv.x*hv.x; a1 += wv.y*hv.y; a2 += wv.z*hv.z; a3 += wv.w*hv.w;
    }
    ghs[g] = (a0+a1)+(a2+a3) + bias;
    __syncthreads();
    if(g<128){
      float rr = sig_acc(gis[g]       + ghs[g]);
      float zz = sig_acc(gis[128+g]   + ghs[128+g]);
      float nn = tanhf (gis[256+g] + rr*ghs[256+g]);
      float hn = (1.0f-zz)*nn + zz*hs[g];
      g_eoT[((size_t)b*SS + s)*HH + g] = hn;
      hs[g] = hn;
    }
    __syncthreads();
    giv = gi_next;
  }
  if(g<128) g_h[b*HH + g] = hs[g];
}

// ---------------- enc_proj = enc_out @ attn_W[:,128:].T + attn_b (rows = [b][s]) ----------------
__global__ void __launch_bounds__(256,2) k_encproj(const float* __restrict__ attnW,
                                                   const float* __restrict__ attnb){
  int t = threadIdx.x;
  int j = t & 127, half = t >> 7;
  float w[64];
  const float4* wp = (const float4*)(attnW + (size_t)j*256 + 128 + half*64);
  #pragma unroll
  for(int i=0;i<16;i++){ float4 q=wp[i]; w[4*i]=q.x; w[4*i+1]=q.y; w[4*i+2]=q.z; w[4*i+3]=q.w; }
  float bias = attnb[j];
  __shared__ float xs[2][128];
  __shared__ float part[2][128];
  const int ROWS = (SS*BB)/512;
  size_t base = (size_t)blockIdx.x * ROWS;
  if(t<128) xs[0][t] = g_eoT[base*HH + t];
  __syncthreads();
  for(int r=0;r<ROWS;r++){
    int cur=r&1, nxt=cur^1;
    if(r+1<ROWS && t<128) xs[nxt][t] = g_eoT[(base+r+1)*HH + t];
    float a0=0,a1=0,a2=0,a3=0;
    const float* xp = &xs[cur][half*64];
    #pragma unroll
    for(int k=0;k<64;k+=4){
      a0+=w[k]*xp[k]; a1+=w[k+1]*xp[k+1]; a2+=w[k+2]*xp[k+2]; a3+=w[k+3]*xp[k+3];
    }
    part[half][j] = (a0+a1)+(a2+a3);
    __syncthreads();
    if(!half) g_epBS[(base+r)*HH + j] = part[0][j] + part[1][j] + bias;
    __syncthreads();
  }
}

// ---------------- per-b transpose enc_proj [b][s][h] -> [b][h][s] ----------------
__global__ void k_trP2(){
  __shared__ float tile[32][33];
  int b = blockIdx.z;
  int s0 = blockIdx.x*32, h0 = blockIdx.y*32;
  int tx = threadIdx.x, ty = threadIdx.y;
  #pragma unroll
  for(int i=0;i<32;i+=8)
    tile[ty+i][tx] = g_epBS[((size_t)b*SS + s0+ty+i)*HH + h0+tx];
  __syncthreads();
  #pragma unroll
  for(int i=0;i<32;i+=8)
    g_epT[((size_t)b*HH + h0+ty+i)*SS + s0+tx] = tile[tx][ty+i];
}

// ---------------- fused decode step: argmax merge + embed + attention + GRU ----------------
__global__ void __launch_bounds__(256,1) k_step(const int* __restrict__ seq,
      const float* __restrict__ emb, const float* __restrict__ attnW,
      const float* __restrict__ attnv, const float* __restrict__ dbih,
      const float* __restrict__ dbhh, int t){
  __shared__ float hs[128], hp[128], part[128], vsd[128];
  __shared__ float xs[192];            // GRU input: emb(64)+ctx(128)
  __shared__ float ws[1024];
  __shared__ float red[40];
  __shared__ float4 cbuf[8][32];
  __shared__ float gi[384], gh[384];
  __shared__ float hnew_s[128];
  __shared__ float sv[8]; __shared__ int si8[8];
  __shared__ int stok;
  int b = blockIdx.x, tid = threadIdx.x;
  int lane = tid&31, warp = tid>>5;

  // ---- token: argmax merge (t>0) or seq[0] ----
  if(t == 0){
    if(tid==0) stok = seq[b];
  } else {
    float v=-3.4e38f; int ix=0x7fffffff;
    for(int idx=tid; idx<NTILES; idx+=256){
      float pv = g_pval[b*512+idx]; int pi = g_pidx[b*512+idx];
      if(pv>v || (pv==v && pi<ix)){ v=pv; ix=pi; }
    }
    #pragma unroll
    for(int o=16;o;o>>=1){
      float ov=__shfl_xor_sync(0xffffffffu,v,o); int oi=__shfl_xor_sync(0xffffffffu,ix,o);
      if(ov>v || (ov==v && oi<ix)){ v=ov; ix=oi; }
    }
    if(lane==0){ sv[warp]=v; si8[warp]=ix; }
    __syncthreads();
    if(tid==0){
      float bv=sv[0]; int bx=si8[0];
      for(int i=1;i<8;i++) if(sv[i]>bv || (sv[i]==bv && si8[i]<bx)){ bv=sv[i]; bx=si8[i]; }
      stok = bx;
    }
  }
  __syncthreads();
  if(tid < 64) xs[tid] = emb[(size_t)stok*EE + tid];
  if(tid < 128){ hs[tid] = g_h[b*HH + tid]; vsd[tid] = attnv[tid]; }
  __syncthreads();

  // ---- hp = h @ attn_W[:, :128].T ----
  {
    int j = tid & 127, half = tid >> 7;
    const float4* wr = (const float4*)(attnW + (size_t)j*256 + half*64);
    const float* hb = &hs[half*64];
    float a = 0.0f;
    #pragma unroll
    for(int i=0;i<16;i++){
      float4 q = wr[i];
      a += q.x*hb[4*i] + q.y*hb[4*i+1] + q.z*hb[4*i+2] + q.w*hb[4*i+3];
    }
    if(half) part[j] = a;
    __syncthreads();
    if(!half) hp[j] = a + part[j];
    __syncthreads();
  }
  // ---- scores (coalesced [b][h][s]) ----
  {
    const float* base = g_epT + (size_t)b*HH*SS;
    float a0=0,a1=0,a2=0,a3=0;
    #pragma unroll 4
    for(int h=0;h<128;h++){
      float hpv = hp[h], vv = vsd[h];
      const float* p = base + (size_t)h*SS + tid;
      float e0 = p[0], e1 = p[256], e2 = p[512], e3 = p[768];
      a0 += tanh_fast(e0+hpv)*vv;
      a1 += tanh_fast(e1+hpv)*vv;
      a2 += tanh_fast(e2+hpv)*vv;
      a3 += tanh_fast(e3+hpv)*vv;
    }
    ws[tid]=a0; ws[tid+256]=a1; ws[tid+512]=a2; ws[tid+768]=a3;
  }
  __syncthreads();
  // ---- softmax ----
  {
    float4 sc = ((float4*)ws)[tid];
    float m = fmaxf(fmaxf(sc.x,sc.y), fmaxf(sc.z,sc.w));
    #pragma unroll
    for(int o=16;o;o>>=1) m = fmaxf(m, __shfl_xor_sync(0xffffffffu,m,o));
    if(lane==0) red[warp] = m;
    __syncthreads();
    if(tid==0){ float mm=red[0]; for(int i=1;i<8;i++) mm=fmaxf(mm,red[i]); red[8]=mm; }
    __syncthreads();
    float M = red[8];
    float4 e;
    e.x=expf(sc.x-M); e.y=expf(sc.y-M); e.z=expf(sc.z-M); e.w=expf(sc.w-M);
    ((float4*)ws)[tid] = e;
    float ssum = (e.x+e.y)+(e.z+e.w);
    #pragma unroll
    for(int o=16;o;o>>=1) ssum += __shfl_xor_sync(0xffffffffu, ssum, o);
    if(lane==0) red[16+warp] = ssum;
    __syncthreads();
    if(tid==0){ float s2=0; for(int i=0;i<8;i++) s2+=red[16+i]; red[24]=s2; }
    __syncthreads();
  }
  float inv = 1.0f / red[24];
  // ---- context (coalesced [b][s][h]) ----
  {
    int hq = tid&31, sg = tid>>5;
    const float* base = g_eoT + (size_t)b*SS*HH;
    float4 acc = make_float4(0,0,0,0);
    #pragma unroll 4
    for(int i=0;i<128;i++){
      int s = sg + (i<<3);
      float wg = ws[s];
      float4 ev = ((const float4*)(base + (size_t)s*HH))[hq];
      acc.x += wg*ev.x; acc.y += wg*ev.y; acc.z += wg*ev.z; acc.w += wg*ev.w;
    }
    cbuf[sg][hq] = acc;
    __syncthreads();
    if(tid<32){
      float4 tot = cbuf[0][tid];
      #pragma unroll
      for(int g2=1;g2<8;g2++){
        float4 c = cbuf[g2][tid];
        tot.x+=c.x; tot.y+=c.y; tot.z+=c.z; tot.w+=c.w;
      }
      tot.x*=inv; tot.y*=inv; tot.z*=inv; tot.w*=inv;
      int h0 = tid*4;
      xs[64+h0]   = tot.x; xs[64+h0+1] = tot.y;
      xs[64+h0+2] = tot.z; xs[64+h0+3] = tot.w;
    }
  }
  __syncthreads();
  // ---- GRU gates: thread j<192 computes gates 2j, 2j+1 ----
  if(tid < 192){
    float a0 = dbih[2*tid], a1 = dbih[2*tid+1];
    #pragma unroll 8
    for(int k=0;k<192;k++){
      float2 w = g_wiT2[k*192 + tid];
      float x = xs[k];
      a0 += w.x*x; a1 += w.y*x;
    }
    float c0 = dbhh[2*tid], c1 = dbhh[2*tid+1];
    #pragma unroll 8
    for(int k=0;k<128;k++){
      float2 w = g_whT2[k*192 + tid];
      float h = hs[k];
      c0 += w.x*h; c1 += w.y*h;
    }
    gi[2*tid]=a0; gi[2*tid+1]=a1;
    gh[2*tid]=c0; gh[2*tid+1]=c1;
  }
  __syncthreads();
  // ---- combine ----
  if(tid < 128){
    float rr = sig_acc(gi[tid]     + gh[tid]);
    float zz = sig_acc(gi[128+tid] + gh[128+tid]);
    float nn = tanhf (gi[256+tid] + rr*gh[256+tid]);
    float hv = (1.0f-zz)*nn + zz*hs[tid];
    g_h[b*HH + tid] = hv;
    hnew_s[tid] = hv;
  }
  __syncthreads();
  // ---- pack xlog = [hnew, ctx] into 3 bf16 splits ----
  if(tid < 128){
    float f0, f1;
    if(tid < 64){ f0 = hnew_s[2*tid]; f1 = hnew_s[2*tid+1]; }
    else        { f0 = xs[64 + 2*tid - 128]; f1 = xs[64 + 2*tid - 127]; }
    uint32_t h,m,l;
    split3(make_float2(f0,f1), h, m, l);
    g_xh[b*128+tid]=h; g_xm[b*128+tid]=m; g_xl[b*128+tid]=l;
  }
}

// ---------------- logits GEMM: ldmatrix + cp.async double buffer + fused argmax ----------------
#define BSTR 528u
#define SPLIT_B (64u*BSTR)         // 33792
#define BUF_B (3u*SPLIT_B)         // 101376
#define LOG_DYN (2*BUF_B)          // 202752
__global__ void __launch_bounds__(256,1) k_logits(const float* __restrict__ outb,
                                                  float* __restrict__ out, int t){
  extern __shared__ char dyn[];
  uint32_t sb = s2u(dyn);
  int tid = threadIdx.x;
  int wid = tid>>5, lane = tid&31;
  int r = lane>>2, tig = lane&3;
  int b0 = wid*16 + r, b1 = b0 + 8;
  uint32_t lrow = (uint32_t)(lane&7) + (uint32_t)((lane>>4)<<3);
  uint32_t lkadd = (uint32_t)(((lane>>3)&1)<<4);
  float* outRow = out + (size_t)t*BB*VV;

  // prologue prefetch
  {
    int t0 = blockIdx.x;
    if(t0 < NTILES){
      int v0 = t0*NT;
      const char* sH = (const char*)g_Wh + (size_t)v0*512;
      const char* sM = (const char*)g_Wm + (size_t)v0*512;
      const char* sL = (const char*)g_Wl + (size_t)v0*512;
      #pragma unroll
      for(int j=0;j<8;j++){
        int idx = tid + j*256;
        uint32_t off = (uint32_t)(idx>>5)*BSTR + (uint32_t)(idx&31)*16u;
        cpasync16(sb + off,             sH + (size_t)idx*16);
        cpasync16(sb + SPLIT_B + off,   sM + (size_t)idx*16);
        cpasync16(sb + 2*SPLIT_B + off, sL + (size_t)idx*16);
      }
    }
    asm volatile("cp.async.commit_group;" ::: "memory");
  }

  int iter = 0;
  for(int tile = blockIdx.x; tile < NTILES; tile += 148, iter ^= 1){
    uint32_t cur  = sb + (iter ? BUF_B : 0u);
    uint32_t nxtb = sb + (iter ? 0u : BUF_B);
    int nxt = tile + 148;
    if(nxt < NTILES){
      int v0n = nxt*NT;
      const char* sH = (const char*)g_Wh + (size_t)v0n*512;
      const char* sM = (const char*)g_Wm + (size_t)v0n*512;
      const char* sL = (const char*)g_Wl + (size_t)v0n*512;
      #pragma unroll
      for(int j=0;j<8;j++){
        int idx = tid + j*256;
        uint32_t off = (uint32_t)(idx>>5)*BSTR + (uint32_t)(idx&31)*16u;
        cpasync16(nxtb + off,             sH + (size_t)idx*16);
        cpasync16(nxtb + SPLIT_B + off,   sM + (size_t)idx*16);
        cpasync16(nxtb + 2*SPLIT_B + off, sL + (size_t)idx*16);
      }
    }
    asm volatile("cp.async.commit_group;" ::: "memory");
    asm volatile("cp.async.wait_group 1;" ::: "memory");
    __syncthreads();

    int v0 = tile*NT;
    float c[8][4];
    #pragma unroll
    for(int i=0;i<8;i++){ c[i][0]=0.f;c[i][1]=0.f;c[i][2]=0.f;c[i][3]=0.f; }

    #pragma unroll
    for(int kc=0;kc<2;kc++){
      // A fragments from pre-split bf16 x
      uint32_t ah[8][4], am[8][4], al[8][4];
      int base0 = b0*128 + kc*64 + tig;
      int base1 = b1*128 + kc*64 + tig;
      #pragma unroll
      for(int ks=0;ks<8;ks++){
        int i0 = base0 + ks*8, i1 = base1 + ks*8;
        ah[ks][0]=g_xh[i0]; ah[ks][1]=g_xh[i1]; ah[ks][2]=g_xh[i0+4]; ah[ks][3]=g_xh[i1+4];
        am[ks][0]=g_xm[i0]; am[ks][1]=g_xm[i1]; am[ks][2]=g_xm[i0+4]; am[ks][3]=g_xm[i1+4];
        al[ks][0]=g_xl[i0]; al[ks][1]=g_xl[i1]; al[ks][2]=g_xl[i0+4]; al[ks][3]=g_xl[i1+4];
      }
      #pragma unroll
      for(int ks=0;ks<8;ks++){
        uint32_t kb = (uint32_t)(kc*128 + ks*16)*2u;
        #pragma unroll
        for(int nsp=0;nsp<4;nsp++){
          uint32_t rowoff = ((uint32_t)nsp*16u + lrow)*BSTR + kb + lkadd;
          uint32_t h0a,h1a,h0b,h1b, m0a,m1a,m0b,m1b, l0a,l1a,l0b,l1b;
          LDSM4(h0a,h1a,h0b,h1b, cur + rowoff);
          LDSM4(m0a,m1a,m0b,m1b, cur + SPLIT_B + rowoff);
          LDSM4(l0a,l1a,l0b,l1b, cur + 2*SPLIT_B + rowoff);
          MMA(c[2*nsp],   ah[ks], h0a,h1a);
          MMA(c[2*nsp],   am[ks], h0a,h1a);
          MMA(c[2*nsp],   al[ks], h0a,h1a);
          MMA(c[2*nsp],   ah[ks], m0a,m1a);
          MMA(c[2*nsp],   am[ks], m0a,m1a);
          MMA(c[2*nsp],   ah[ks], l0a,l1a);
          MMA(c[2*nsp+1], ah[ks], h0b,h1b);
          MMA(c[2*nsp+1], am[ks], h0b,h1b);
          MMA(c[2*nsp+1], al[ks], h0b,h1b);
          MMA(c[2*nsp+1], ah[ks], m0b,m1b);
          MMA(c[2*nsp+1], am[ks], m0b,m1b);
          MMA(c[2*nsp+1], ah[ks], l0b,l1b);
        }
      }
    }
    // epilogue: bias + store + per-row argmax partial
    float bv0=-3.4e38f, bv1=-3.4e38f; int bi0=0x7fffffff, bi1=0x7fffffff;
    #pragma unroll
    for(int ns=0;ns<8;ns++){
      int n = ns*8 + tig*2;
      float2 bb = *(const float2*)(outb + v0 + n);
      float f0 = c[ns][0] + bb.x;
      float f1 = c[ns][1] + bb.y;
      float f2 = c[ns][2] + bb.x;
      float f3 = c[ns][3] + bb.y;
      if(f0>bv0){bv0=f0;bi0=v0+n;}
      if(f1>bv0){bv0=f1;bi0=v0+n+1;}
      if(f2>bv1){bv1=f2;bi1=v0+n;}
      if(f3>bv1){bv1=f3;bi1=v0+n+1;}
      *(float2*)(outRow + (size_t)b0*VV + v0 + n) = make_float2(f0,f1);
      *(float2*)(outRow + (size_t)b1*VV + v0 + n) = make_float2(f2,f3);
    }
    #pragma unroll
    for(int o=1;o<4;o<<=1){
      float ov0=__shfl_xor_sync(0xffffffffu,bv0,o); int oi0=__shfl_xor_sync(0xffffffffu,bi0,o);
      float ov1=__shfl_xor_sync(0xffffffffu,bv1,o); int oi1=__shfl_xor_sync(0xffffffffu,bi1,o);
      if(ov0>bv0||(ov0==bv0&&oi0<bi0)){bv0=ov0;bi0=oi0;}
      if(ov1>bv1||(ov1==bv1&&oi1<bi1)){bv1=ov1;bi1=oi1;}
    }
    if(tig==0){
      g_pval[b0*512 + tile]=bv0; g_pidx[b0*512 + tile]=bi0;
      g_pval[b1*512 + tile]=bv1; g_pidx[b1*512 + tile]=bi1;
    }
    __syncthreads();
  }
}

// ---------------- launch ----------------
extern "C" void kernel_launch(void* const* d_in, const int* in_sizes, int n_in,
                              void* d_out, int out_size) {
  const int*   seq     = (const int*)  d_in[0];
  const float* emb     = (const float*)d_in[2];
  const float* encWih  = (const float*)d_in[3];
  const float* encWhh  = (const float*)d_in[4];
  const float* encbih  = (const float*)d_in[5];
  const float* encbhh  = (const float*)d_in[6];
  const float* attnW   = (const float*)d_in[7];
  const float* attnb   = (const float*)d_in[8];
  const float* attnv   = (const float*)d_in[9];
  const float* dWih    = (const float*)d_in[10];
  const float* dWhh    = (const float*)d_in[11];
  const float* dbih    = (const float*)d_in[12];
  const float* dbhh    = (const float*)d_in[13];
  const float* outW    = (const float*)d_in[14];
  const float* outb    = (const float*)d_in[15];
  float* out = (float*)d_out;

  const int ENC_SMEM = (12288 + 128 + 384 + 384) * 4;
  cudaFuncSetAttribute(k_encrec, cudaFuncAttributeMaxDynamicSharedMemorySize, ENC_SMEM);
  cudaFuncSetAttribute(k_logits, cudaFuncAttributeMaxDynamicSharedMemorySize, LOG_DYN);

  // setup
  k_wsplit<<<8000, 256>>>(outW);
  k_wtrans<<<240, 256>>>(dWih, dWhh);
  k_giall<<<512, 384>>>(seq, emb, encWih, encbih);
  k_encrec<<<128, 384, ENC_SMEM>>>(encWhh, encbhh);
  k_encproj<<<512, 256>>>(attnW, attnb);
  k_trP2<<<dim3(32,4,128), dim3(32,8)>>>();

  // decode: 2 kernels per step
  for(int t=0; t<TT; t++){
    k_step<<<128, 256>>>(seq, emb, attnW, attnv, dbih, dbhh, t);
    k_logits<<<148, 256, LOG_DYN>>>(outb, out, t);
  }
}

// round 8
// speedup vs baseline: 1.6368x; 1.1216x over previous
#include <cuda_runtime.h>
#include <cuda_bf16.h>
#include <cuda_fp16.h>
#include <math.h>
#include <stdint.h>

#define VV 32000
#define EE 64
#define HH 128
#define SS 1024
#define BB 128
#define TT 64
#define GG 384
#define NT 64
#define NTILES 500        // VV / NT

// ---------------- device scratch ----------------
__device__ float g_gi[(size_t)SS*BB*GG];
__device__ float g_eoT[(size_t)BB*SS*HH];     // enc_out [b][s][h]
__device__ float g_epBS[(size_t)BB*SS*HH];    // enc_proj [b][s][h]
__device__ float g_epT[(size_t)BB*HH*SS];     // enc_proj [b][h][s]
__device__ __half g_Wh[(size_t)VV*256];       // fp16 high split [v][k]
__device__ __half g_Wm[(size_t)VV*256];       // fp16 residual * 2048
__device__ float2 g_wiT2[192*192];            // [k][jpair] of dec_Wih
__device__ float2 g_whT2[128*192];            // [k][jpair] of dec_Whh
__device__ float g_h[BB*HH];
__device__ uint32_t g_xh[BB*128];             // x fp16x2 high split [b][pair]
__device__ uint32_t g_xm[BB*128];             // x fp16x2 residual*2048
__device__ float g_pval[BB*512];
__device__ int   g_pidx[BB*512];

__device__ __forceinline__ float sig_acc(float x){ return 1.0f/(1.0f + expf(-x)); }
__device__ __forceinline__ float tanh_fast(float x){
  return 1.0f - __fdividef(2.0f, __expf(2.0f*x) + 1.0f);
}

// ---------------- helpers ----------------
__device__ __forceinline__ uint32_t s2u(const void* p){
  uint32_t a;
  asm("{ .reg .u64 t; cvta.to.shared.u64 t, %1; cvt.u32.u64 %0, t; }" : "=r"(a) : "l"(p));
  return a;
}
__device__ __forceinline__ uint32_t pack_h2(__half lo, __half hi){
  __half2 t = __halves2half2(lo, hi);
  return *(uint32_t*)&t;
}
// 2-way fp16 split; residual scaled by 2^11 to stay in fp16 normal range
__device__ __forceinline__ void split2h(float2 f, uint32_t& h, uint32_t& m){
  __half h0=__float2half_rn(f.x), h1=__float2half_rn(f.y);
  float r0=(f.x-__half2float(h0))*2048.0f, r1=(f.y-__half2float(h1))*2048.0f;
  h = pack_h2(h0,h1);
  m = pack_h2(__float2half_rn(r0), __float2half_rn(r1));
}
__device__ __forceinline__ void cpasync16(uint32_t saddr, const void* gaddr){
  asm volatile("cp.async.cg.shared.global [%0], [%1], 16;" :: "r"(saddr), "l"(gaddr) : "memory");
}

#define MMA(cc, aa, bb0, bb1) \
  asm volatile("mma.sync.aligned.m16n8k16.row.col.f32.f16.f16.f32 " \
    "{%0,%1,%2,%3}, {%4,%5,%6,%7}, {%8,%9}, {%0,%1,%2,%3};" \
    : "+f"(cc[0]),"+f"(cc[1]),"+f"(cc[2]),"+f"(cc[3]) \
    : "r"(aa[0]),"r"(aa[1]),"r"(aa[2]),"r"(aa[3]), "r"(bb0),"r"(bb1))

#define LDSM4(r0,r1,r2,r3,addr) \
  asm volatile("ldmatrix.sync.aligned.m8n8.x4.shared.b16 {%0,%1,%2,%3}, [%4];" \
    : "=r"(r0),"=r"(r1),"=r"(r2),"=r"(r3) : "r"(addr))

// ---------------- setup: split out_W into 2 fp16 levels ----------------
__global__ void k_wsplit(const float* __restrict__ outW){
  size_t i4 = (size_t)blockIdx.x*256 + threadIdx.x;   // float4 index
  float4 w = ((const float4*)outW)[i4];
  uint2 uh, um;
  split2h(make_float2(w.x,w.y), uh.x, um.x);
  split2h(make_float2(w.z,w.w), uh.y, um.y);
  ((uint2*)g_Wh)[i4] = uh;
  ((uint2*)g_Wm)[i4] = um;
}

// ---------------- setup: transpose decoder GRU weights into [k][jpair] ----------------
__global__ void k_wtrans(const float* __restrict__ dWih, const float* __restrict__ dWhh){
  int idx = blockIdx.x*256 + threadIdx.x;
  if(idx < 192*192){
    int k = idx/192, j = idx%192;
    g_wiT2[idx] = make_float2(dWih[(size_t)(2*j)*192+k], dWih[(size_t)(2*j+1)*192+k]);
  } else {
    int i2 = idx - 192*192;
    if(i2 < 128*192){
      int k = i2/192, j = i2%192;
      g_whT2[i2] = make_float2(dWhh[(size_t)(2*j)*128+k], dWhh[(size_t)(2*j+1)*128+k]);
    }
  }
}

// ---------------- encoder input projection ----------------
__global__ void __launch_bounds__(384,2) k_giall(const int* __restrict__ seq,
      const float* __restrict__ emb, const float* __restrict__ Wih,
      const float* __restrict__ bih){
  int g = threadIdx.x;
  float w[64];
  const float4* wp = (const float4*)(Wih + (size_t)g*64);
  #pragma unroll
  for(int i=0;i<16;i++){ float4 q=wp[i]; w[4*i]=q.x; w[4*i+1]=q.y; w[4*i+2]=q.z; w[4*i+3]=q.w; }
  float bias = bih[g];
  __shared__ float xs[2][64];
  const int ROWS = (SS*BB)/512;   // 256
  size_t base = (size_t)blockIdx.x * ROWS;
  if(g<64){ int tok0 = seq[base]; xs[0][g] = emb[(size_t)tok0*EE + g]; }
  __syncthreads();
  for(int r=0;r<ROWS;r++){
    int cur=r&1, nxt=cur^1;
    if(r+1<ROWS && g<64){
      int tok2 = seq[base+r+1];
      xs[nxt][g] = emb[(size_t)tok2*EE + g];
    }
    float a0=0,a1=0,a2=0,a3=0;
    #pragma unroll
    for(int k=0;k<64;k+=4){
      a0 += w[k]*xs[cur][k];     a1 += w[k+1]*xs[cur][k+1];
      a2 += w[k+2]*xs[cur][k+2]; a3 += w[k+3]*xs[cur][k+3];
    }
    g_gi[(base+r)*GG + g] = (a0+a1)+(a2+a3) + bias;
    __syncthreads();
  }
}

// ---------------- encoder recurrence (writes enc_out transposed [b][s][h]) ----------------
__global__ void __launch_bounds__(384,1) k_encrec(const float* __restrict__ Whh,
      const float* __restrict__ bhh){
  extern __shared__ float sm[];
  float* whh_s = sm;
  float* hs    = sm + 12288;
  float* ghs   = hs + 128;
  float* gis   = ghs + 384;
  int b = blockIdx.x;
  int g = threadIdx.x;
  float w[96];
  {
    const float4* wlo = (const float4*)(Whh + (size_t)g*128);
    #pragma unroll
    for(int i=0;i<24;i++){ float4 q=wlo[i]; w[4*i]=q.x; w[4*i+1]=q.y; w[4*i+2]=q.z; w[4*i+3]=q.w; }
    const float4* whi = (const float4*)(Whh + (size_t)g*128 + 96);
    #pragma unroll
    for(int i=0;i<8;i++) ((float4*)whh_s)[i*384 + g] = whi[i];
  }
  float bias = bhh[g];
  if(g<128) hs[g] = 0.0f;
  __syncthreads();

  float giv = g_gi[(size_t)b*GG + g];
  for(int s=0;s<SS;s++){
    float gi_next = 0.0f;
    if(s+1<SS) gi_next = g_gi[((size_t)(s+1)*BB + b)*GG + g];
    gis[g] = giv;
    float a0=0,a1=0,a2=0,a3=0;
    #pragma unroll
    for(int i=0;i<24;i++){
      float4 hv = ((float4*)hs)[i];
      a0 += w[4*i]*hv.x;   a1 += w[4*i+1]*hv.y;
      a2 += w[4*i+2]*hv.z; a3 += w[4*i+3]*hv.w;
    }
    #pragma unroll
    for(int i=0;i<8;i++){
      float4 wv = ((float4*)whh_s)[i*384 + g];
      float4 hv = ((float4*)hs)[24 + i];
      a0 += wv.x*hv.x; a1 += wv.y*hv.y; a2 += wv.z*hv.z; a3 += wv.w*hv.w;
    }
    ghs[g] = (a0+a1)+(a2+a3) + bias;
    __syncthreads();
    if(g<128){
      float rr = sig_acc(gis[g]       + ghs[g]);
      float zz = sig_acc(gis[128+g]   + ghs[128+g]);
      float nn = tanhf (gis[256+g] + rr*ghs[256+g]);
      float hn = (1.0f-zz)*nn + zz*hs[g];
      g_eoT[((size_t)b*SS + s)*HH + g] = hn;
      hs[g] = hn;
    }
    __syncthreads();
    giv = gi_next;
  }
  if(g<128) g_h[b*HH + g] = hs[g];
}

// ---------------- enc_proj = enc_out @ attn_W[:,128:].T + attn_b (rows = [b][s]) ----------------
__global__ void __launch_bounds__(256,2) k_encproj(const float* __restrict__ attnW,
                                                   const float* __restrict__ attnb){
  int t = threadIdx.x;
  int j = t & 127, half = t >> 7;
  float w[64];
  const float4* wp = (const float4*)(attnW + (size_t)j*256 + 128 + half*64);
  #pragma unroll
  for(int i=0;i<16;i++){ float4 q=wp[i]; w[4*i]=q.x; w[4*i+1]=q.y; w[4*i+2]=q.z; w[4*i+3]=q.w; }
  float bias = attnb[j];
  __shared__ float xs[2][128];
  __shared__ float part[2][128];
  const int ROWS = (SS*BB)/512;
  size_t base = (size_t)blockIdx.x * ROWS;
  if(t<128) xs[0][t] = g_eoT[base*HH + t];
  __syncthreads();
  for(int r=0;r<ROWS;r++){
    int cur=r&1, nxt=cur^1;
    if(r+1<ROWS && t<128) xs[nxt][t] = g_eoT[(base+r+1)*HH + t];
    float a0=0,a1=0,a2=0,a3=0;
    const float* xp = &xs[cur][half*64];
    #pragma unroll
    for(int k=0;k<64;k+=4){
      a0+=w[k]*xp[k]; a1+=w[k+1]*xp[k+1]; a2+=w[k+2]*xp[k+2]; a3+=w[k+3]*xp[k+3];
    }
    part[half][j] = (a0+a1)+(a2+a3);
    __syncthreads();
    if(!half) g_epBS[(base+r)*HH + j] = part[0][j] + part[1][j] + bias;
    __syncthreads();
  }
}

// ---------------- per-b transpose enc_proj [b][s][h] -> [b][h][s] ----------------
__global__ void k_trP2(){
  __shared__ float tile[32][33];
  int b = blockIdx.z;
  int s0 = blockIdx.x*32, h0 = blockIdx.y*32;
  int tx = threadIdx.x, ty = threadIdx.y;
  #pragma unroll
  for(int i=0;i<32;i+=8)
    tile[ty+i][tx] = g_epBS[((size_t)b*SS + s0+ty+i)*HH + h0+tx];
  __syncthreads();
  #pragma unroll
  for(int i=0;i<32;i+=8)
    g_epT[((size_t)b*HH + h0+ty+i)*SS + s0+tx] = tile[tx][ty+i];
}

// ---------------- fused decode step: argmax merge + embed + attention + GRU ----------------
__global__ void __launch_bounds__(256,1) k_step(const int* __restrict__ seq,
      const float* __restrict__ emb, const float* __restrict__ attnW,
      const float* __restrict__ attnv, const float* __restrict__ dbih,
      const float* __restrict__ dbhh, int t){
  __shared__ float hs[128], hp[128], part[128], vsd[128];
  __shared__ float xs[192];            // GRU input: emb(64)+ctx(128)
  __shared__ float ws[1024];
  __shared__ float red[40];
  __shared__ float4 cbuf[8][32];
  __shared__ float gi[384], gh[384];
  __shared__ float hnew_s[128];
  __shared__ float sv[8]; __shared__ int si8[8];
  __shared__ int stok;
  int b = blockIdx.x, tid = threadIdx.x;
  int lane = tid&31, warp = tid>>5;

  // ---- token: argmax merge (t>0) or seq[0] ----
  if(t == 0){
    if(tid==0) stok = seq[b];
  } else {
    float v=-3.4e38f; int ix=0x7fffffff;
    for(int idx=tid; idx<NTILES; idx+=256){
      float pv = g_pval[b*512+idx]; int pi = g_pidx[b*512+idx];
      if(pv>v || (pv==v && pi<ix)){ v=pv; ix=pi; }
    }
    #pragma unroll
    for(int o=16;o;o>>=1){
      float ov=__shfl_xor_sync(0xffffffffu,v,o); int oi=__shfl_xor_sync(0xffffffffu,ix,o);
      if(ov>v || (ov==v && oi<ix)){ v=ov; ix=oi; }
    }
    if(lane==0){ sv[warp]=v; si8[warp]=ix; }
    __syncthreads();
    if(tid==0){
      float bv=sv[0]; int bx=si8[0];
      for(int i=1;i<8;i++) if(sv[i]>bv || (sv[i]==bv && si8[i]<bx)){ bv=sv[i]; bx=si8[i]; }
      stok = bx;
    }
  }
  __syncthreads();
  if(tid < 64) xs[tid] = emb[(size_t)stok*EE + tid];
  if(tid < 128){ hs[tid] = g_h[b*HH + tid]; vsd[tid] = attnv[tid]; }
  __syncthreads();

  // ---- hp = h @ attn_W[:, :128].T ----
  {
    int j = tid & 127, half = tid >> 7;
    const float4* wr = (const float4*)(attnW + (size_t)j*256 + half*64);
    const float* hb = &hs[half*64];
    float a = 0.0f;
    #pragma unroll
    for(int i=0;i<16;i++){
      float4 q = wr[i];
      a += q.x*hb[4*i] + q.y*hb[4*i+1] + q.z*hb[4*i+2] + q.w*hb[4*i+3];
    }
    if(half) part[j] = a;
    __syncthreads();
    if(!half) hp[j] = a + part[j];
    __syncthreads();
  }
  // ---- scores (coalesced [b][h][s]) ----
  {
    const float* base = g_epT + (size_t)b*HH*SS;
    float a0=0,a1=0,a2=0,a3=0;
    #pragma unroll 4
    for(int h=0;h<128;h++){
      float hpv = hp[h], vv = vsd[h];
      const float* p = base + (size_t)h*SS + tid;
      float e0 = p[0], e1 = p[256], e2 = p[512], e3 = p[768];
      a0 += tanh_fast(e0+hpv)*vv;
      a1 += tanh_fast(e1+hpv)*vv;
      a2 += tanh_fast(e2+hpv)*vv;
      a3 += tanh_fast(e3+hpv)*vv;
    }
    ws[tid]=a0; ws[tid+256]=a1; ws[tid+512]=a2; ws[tid+768]=a3;
  }
  __syncthreads();
  // ---- softmax ----
  {
    float4 sc = ((float4*)ws)[tid];
    float m = fmaxf(fmaxf(sc.x,sc.y), fmaxf(sc.z,sc.w));
    #pragma unroll
    for(int o=16;o;o>>=1) m = fmaxf(m, __shfl_xor_sync(0xffffffffu,m,o));
    if(lane==0) red[warp] = m;
    __syncthreads();
    if(tid==0){ float mm=red[0]; for(int i=1;i<8;i++) mm=fmaxf(mm,red[i]); red[8]=mm; }
    __syncthreads();
    float M = red[8];
    float4 e;
    e.x=expf(sc.x-M); e.y=expf(sc.y-M); e.z=expf(sc.z-M); e.w=expf(sc.w-M);
    ((float4*)ws)[tid] = e;
    float ssum = (e.x+e.y)+(e.z+e.w);
    #pragma unroll
    for(int o=16;o;o>>=1) ssum += __shfl_xor_sync(0xffffffffu, ssum, o);
    if(lane==0) red[16+warp] = ssum;
    __syncthreads();
    if(tid==0){ float s2=0; for(int i=0;i<8;i++) s2+=red[16+i]; red[24]=s2; }
    __syncthreads();
  }
  float inv = 1.0f / red[24];
  // ---- context (coalesced [b][s][h]) ----
  {
    int hq = tid&31, sg = tid>>5;
    const float* base = g_eoT + (size_t)b*SS*HH;
    float4 acc = make_float4(0,0,0,0);
    #pragma unroll 4
    for(int i=0;i<128;i++){
      int s = sg + (i<<3);
      float wg = ws[s];
      float4 ev = ((const float4*)(base + (size_t)s*HH))[hq];
      acc.x += wg*ev.x; acc.y += wg*ev.y; acc.z += wg*ev.z; acc.w += wg*ev.w;
    }
    cbuf[sg][hq] = acc;
    __syncthreads();
    if(tid<32){
      float4 tot = cbuf[0][tid];
      #pragma unroll
      for(int g2=1;g2<8;g2++){
        float4 c = cbuf[g2][tid];
        tot.x+=c.x; tot.y+=c.y; tot.z+=c.z; tot.w+=c.w;
      }
      tot.x*=inv; tot.y*=inv; tot.z*=inv; tot.w*=inv;
      int h0 = tid*4;
      xs[64+h0]   = tot.x; xs[64+h0+1] = tot.y;
      xs[64+h0+2] = tot.z; xs[64+h0+3] = tot.w;
    }
  }
  __syncthreads();
  // ---- GRU gates: thread j<192 computes gates 2j, 2j+1 ----
  if(tid < 192){
    float a0 = dbih[2*tid], a1 = dbih[2*tid+1];
    #pragma unroll 8
    for(int k=0;k<192;k++){
      float2 w = g_wiT2[k*192 + tid];
      float x = xs[k];
      a0 += w.x*x; a1 += w.y*x;
    }
    float c0 = dbhh[2*tid], c1 = dbhh[2*tid+1];
    #pragma unroll 8
    for(int k=0;k<128;k++){
      float2 w = g_whT2[k*192 + tid];
      float h = hs[k];
      c0 += w.x*h; c1 += w.y*h;
    }
    gi[2*tid]=a0; gi[2*tid+1]=a1;
    gh[2*tid]=c0; gh[2*tid+1]=c1;
  }
  __syncthreads();
  // ---- combine ----
  if(tid < 128){
    float rr = sig_acc(gi[tid]     + gh[tid]);
    float zz = sig_acc(gi[128+tid] + gh[128+tid]);
    float nn = tanhf (gi[256+tid] + rr*gh[256+tid]);
    float hv = (1.0f-zz)*nn + zz*hs[tid];
    g_h[b*HH + tid] = hv;
    hnew_s[tid] = hv;
  }
  __syncthreads();
  // ---- pack xlog = [hnew, ctx] into 2 fp16 splits ----
  if(tid < 128){
    float f0, f1;
    if(tid < 64){ f0 = hnew_s[2*tid]; f1 = hnew_s[2*tid+1]; }
    else        { f0 = xs[64 + 2*tid - 128]; f1 = xs[64 + 2*tid - 127]; }
    uint32_t h,m;
    split2h(make_float2(f0,f1), h, m);
    g_xh[b*128+tid]=h; g_xm[b*128+tid]=m;
  }
}

// ---------------- logits GEMM: fp16 2-split, 3 products, cp.async db + fused argmax ----------------
#define BSTR 528u
#define SPLIT_B (64u*BSTR)         // 33792
#define BUF_B (2u*SPLIT_B)         // 67584
#define LOG_DYN (2*BUF_B)          // 135168
__global__ void __launch_bounds__(256,1) k_logits(const float* __restrict__ outb,
                                                  float* __restrict__ out, int t){
  extern __shared__ char dyn[];
  uint32_t sb = s2u(dyn);
  int tid = threadIdx.x;
  int wid = tid>>5, lane = tid&31;
  int r = lane>>2, tig = lane&3;
  int b0 = wid*16 + r, b1 = b0 + 8;
  uint32_t lrow = (uint32_t)(lane&7) + (uint32_t)((lane>>4)<<3);
  uint32_t lkadd = (uint32_t)(((lane>>3)&1)<<4);
  float* outRow = out + (size_t)t*BB*VV;
  const float INVS = 1.0f/2048.0f;

  // prologue prefetch
  {
    int t0 = blockIdx.x;
    if(t0 < NTILES){
      int v0 = t0*NT;
      const char* sH = (const char*)g_Wh + (size_t)v0*512;
      const char* sM = (const char*)g_Wm + (size_t)v0*512;
      #pragma unroll
      for(int j=0;j<8;j++){
        int idx = tid + j*256;
        uint32_t off = (uint32_t)(idx>>5)*BSTR + (uint32_t)(idx&31)*16u;
        cpasync16(sb + off,           sH + (size_t)idx*16);
        cpasync16(sb + SPLIT_B + off, sM + (size_t)idx*16);
      }
    }
    asm volatile("cp.async.commit_group;" ::: "memory");
  }

  int iter = 0;
  for(int tile = blockIdx.x; tile < NTILES; tile += 148, iter ^= 1){
    uint32_t cur  = sb + (iter ? BUF_B : 0u);
    uint32_t nxtb = sb + (iter ? 0u : BUF_B);
    int nxt = tile + 148;
    if(nxt < NTILES){
      int v0n = nxt*NT;
      const char* sH = (const char*)g_Wh + (size_t)v0n*512;
      const char* sM = (const char*)g_Wm + (size_t)v0n*512;
      #pragma unroll
      for(int j=0;j<8;j++){
        int idx = tid + j*256;
        uint32_t off = (uint32_t)(idx>>5)*BSTR + (uint32_t)(idx&31)*16u;
        cpasync16(nxtb + off,           sH + (size_t)idx*16);
        cpasync16(nxtb + SPLIT_B + off, sM + (size_t)idx*16);
      }
    }
    asm volatile("cp.async.commit_group;" ::: "memory");
    asm volatile("cp.async.wait_group 1;" ::: "memory");
    __syncthreads();

    int v0 = tile*NT;
    float c1[8][4], c2[8][4];
    #pragma unroll
    for(int i=0;i<8;i++){
      c1[i][0]=0.f;c1[i][1]=0.f;c1[i][2]=0.f;c1[i][3]=0.f;
      c2[i][0]=0.f;c2[i][1]=0.f;c2[i][2]=0.f;c2[i][3]=0.f;
    }

    #pragma unroll
    for(int kc=0;kc<2;kc++){
      // A fragments from pre-split fp16 x
      uint32_t ah[8][4], am[8][4];
      int base0 = b0*128 + kc*64 + tig;
      int base1 = b1*128 + kc*64 + tig;
      #pragma unroll
      for(int ks=0;ks<8;ks++){
        int i0 = base0 + ks*8, i1 = base1 + ks*8;
        ah[ks][0]=g_xh[i0]; ah[ks][1]=g_xh[i1]; ah[ks][2]=g_xh[i0+4]; ah[ks][3]=g_xh[i1+4];
        am[ks][0]=g_xm[i0]; am[ks][1]=g_xm[i1]; am[ks][2]=g_xm[i0+4]; am[ks][3]=g_xm[i1+4];
      }
      #pragma unroll
      for(int ks=0;ks<8;ks++){
        uint32_t kb = (uint32_t)(kc*128 + ks*16)*2u;
        #pragma unroll
        for(int nsp=0;nsp<4;nsp++){
          uint32_t rowoff = ((uint32_t)nsp*16u + lrow)*BSTR + kb + lkadd;
          uint32_t h0a,h1a,h0b,h1b, m0a,m1a,m0b,m1b;
          LDSM4(h0a,h1a,h0b,h1b, cur + rowoff);
          LDSM4(m0a,m1a,m0b,m1b, cur + SPLIT_B + rowoff);
          // acc1 += Xh*Wh ; acc2 += Xh*Wm + Xm*Wh   (acc2 scaled by 2^11)
          MMA(c1[2*nsp],   ah[ks], h0a,h1a);
          MMA(c2[2*nsp],   ah[ks], m0a,m1a);
          MMA(c2[2*nsp],   am[ks], h0a,h1a);
          MMA(c1[2*nsp+1], ah[ks], h0b,h1b);
          MMA(c2[2*nsp+1], ah[ks], m0b,m1b);
          MMA(c2[2*nsp+1], am[ks], h0b,h1b);
        }
      }
    }
    // epilogue: combine scales + bias + store + per-row argmax partial
    float bv0=-3.4e38f, bv1=-3.4e38f; int bi0=0x7fffffff, bi1=0x7fffffff;
    #pragma unroll
    for(int ns=0;ns<8;ns++){
      int n = ns*8 + tig*2;
      float2 bb = *(const float2*)(outb + v0 + n);
      float f0 = c1[ns][0] + c2[ns][0]*INVS + bb.x;
      float f1 = c1[ns][1] + c2[ns][1]*INVS + bb.y;
      float f2 = c1[ns][2] + c2[ns][2]*INVS + bb.x;
      float f3 = c1[ns][3] + c2[ns][3]*INVS + bb.y;
      if(f0>bv0){bv0=f0;bi0=v0+n;}
      if(f1>bv0){bv0=f1;bi0=v0+n+1;}
      if(f2>bv1){bv1=f2;bi1=v0+n;}
      if(f3>bv1){bv1=f3;bi1=v0+n+1;}
      *(float2*)(outRow + (size_t)b0*VV + v0 + n) = make_float2(f0,f1);
      *(float2*)(outRow + (size_t)b1*VV + v0 + n) = make_float2(f2,f3);
    }
    #pragma unroll
    for(int o=1;o<4;o<<=1){
      float ov0=__shfl_xor_sync(0xffffffffu,bv0,o); int oi0=__shfl_xor_sync(0xffffffffu,bi0,o);
      float ov1=__shfl_xor_sync(0xffffffffu,bv1,o); int oi1=__shfl_xor_sync(0xffffffffu,bi1,o);
      if(ov0>bv0||(ov0==bv0&&oi0<bi0)){bv0=ov0;bi0=oi0;}
      if(ov1>bv1||(ov1==bv1&&oi1<bi1)){bv1=ov1;bi1=oi1;}
    }
    if(tig==0){
      g_pval[b0*512 + tile]=bv0; g_pidx[b0*512 + tile]=bi0;
      g_pval[b1*512 + tile]=bv1; g_pidx[b1*512 + tile]=bi1;
    }
    __syncthreads();
  }
}

// ---------------- launch ----------------
extern "C" void kernel_launch(void* const* d_in, const int* in_sizes, int n_in,
                              void* d_out, int out_size) {
  const int*   seq     = (const int*)  d_in[0];
  const float* emb     = (const float*)d_in[2];
  const float* encWih  = (const float*)d_in[3];
  const float* encWhh  = (const float*)d_in[4];
  const float* encbih  = (const float*)d_in[5];
  const float* encbhh  = (const float*)d_in[6];
  const float* attnW   = (const float*)d_in[7];
  const float* attnb   = (const float*)d_in[8];
  const float* attnv   = (const float*)d_in[9];
  const float* dWih    = (const float*)d_in[10];
  const float* dWhh    = (const float*)d_in[11];
  const float* dbih    = (const float*)d_in[12];
  const float* dbhh    = (const float*)d_in[13];
  const float* outW    = (const float*)d_in[14];
  const float* outb    = (const float*)d_in[15];
  float* out = (float*)d_out;

  const int ENC_SMEM = (12288 + 128 + 384 + 384) * 4;
  cudaFuncSetAttribute(k_encrec, cudaFuncAttributeMaxDynamicSharedMemorySize, ENC_SMEM);
  cudaFuncSetAttribute(k_logits, cudaFuncAttributeMaxDynamicSharedMemorySize, LOG_DYN);

  // setup
  k_wsplit<<<8000, 256>>>(outW);
  k_wtrans<<<240, 256>>>(dWih, dWhh);
  k_giall<<<512, 384>>>(seq, emb, encWih, encbih);
  k_encrec<<<128, 384, ENC_SMEM>>>(encWhh, encbhh);
  k_encproj<<<512, 256>>>(attnW, attnb);
  k_trP2<<<dim3(32,4,128), dim3(32,8)>>>();

  // decode: 2 kernels per step
  for(int t=0; t<TT; t++){
    k_step<<<128, 256>>>(seq, emb, attnW, attnv, dbih, dbhh, t);
    k_logits<<<148, 256, LOG_DYN>>>(outb, out, t);
  }
}

// round 9
// speedup vs baseline: 1.8639x; 1.1387x over previous
#include <cuda_runtime.h>
#include <cuda_bf16.h>
#include <cuda_fp16.h>
#include <math.h>
#include <stdint.h>

#define VV 32000
#define EE 64
#define HH 128
#define SS 1024
#define BB 128
#define TT 64
#define GG 384
#define NT2 32
#define NTILES2 1000       // VV / NT2

// ---------------- device scratch ----------------
__device__ float g_gi[(size_t)SS*BB*GG];
__device__ float g_eoT[(size_t)BB*SS*HH];     // enc_out [b][s][h]
__device__ float g_epBS[(size_t)BB*SS*HH];    // enc_proj [b][s][h]
__device__ float g_epT[(size_t)BB*HH*SS];     // enc_proj [b][h][s]
__device__ __half g_Wh[(size_t)VV*256];       // fp16 high split [v][k]
__device__ __half g_Wm[(size_t)VV*256];       // fp16 residual * 2048
__device__ float2 g_wiT2[192*192];            // [k][jpair] of dec_Wih
__device__ float2 g_whT2[128*192];            // [k][jpair] of dec_Whh
__device__ float g_h[BB*HH];
__device__ float g_ctx[BB*HH];                // ctx for current step
__device__ float g_gh[BB*GG];                 // Whh . h (no bias)
__device__ float g_gic[BB*GG];                // Wih[:,64:] . ctx (no bias)
__device__ uint32_t g_xh[BB*128];             // x fp16x2 high split [b][pair]
__device__ uint32_t g_xm[BB*128];             // x fp16x2 residual*2048
__device__ float g_pval[BB*1024];
__device__ int   g_pidx[BB*1024];
__device__ int   g_tilectr;

__device__ __forceinline__ float sig_acc(float x){ return 1.0f/(1.0f + expf(-x)); }
__device__ __forceinline__ float tanh_fast(float x){
  return 1.0f - __fdividef(2.0f, __expf(2.0f*x) + 1.0f);
}

// ---------------- helpers ----------------
__device__ __forceinline__ uint32_t s2u(const void* p){
  uint32_t a;
  asm("{ .reg .u64 t; cvta.to.shared.u64 t, %1; cvt.u32.u64 %0, t; }" : "=r"(a) : "l"(p));
  return a;
}
__device__ __forceinline__ uint32_t pack_h2(__half lo, __half hi){
  __half2 t = __halves2half2(lo, hi);
  return *(uint32_t*)&t;
}
__device__ __forceinline__ void split2h(float2 f, uint32_t& h, uint32_t& m){
  __half h0=__float2half_rn(f.x), h1=__float2half_rn(f.y);
  float r0=(f.x-__half2float(h0))*2048.0f, r1=(f.y-__half2float(h1))*2048.0f;
  h = pack_h2(h0,h1);
  m = pack_h2(__float2half_rn(r0), __float2half_rn(r1));
}
__device__ __forceinline__ void cpasync16(uint32_t saddr, const void* gaddr){
  asm volatile("cp.async.cg.shared.global [%0], [%1], 16;" :: "r"(saddr), "l"(gaddr) : "memory");
}

#define MMA(cc, aa, bb0, bb1) \
  asm volatile("mma.sync.aligned.m16n8k16.row.col.f32.f16.f16.f32 " \
    "{%0,%1,%2,%3}, {%4,%5,%6,%7}, {%8,%9}, {%0,%1,%2,%3};" \
    : "+f"(cc[0]),"+f"(cc[1]),"+f"(cc[2]),"+f"(cc[3]) \
    : "r"(aa[0]),"r"(aa[1]),"r"(aa[2]),"r"(aa[3]), "r"(bb0),"r"(bb1))

#define LDSM4(r0,r1,r2,r3,addr) \
  asm volatile("ldmatrix.sync.aligned.m8n8.x4.shared.b16 {%0,%1,%2,%3}, [%4];" \
    : "=r"(r0),"=r"(r1),"=r"(r2),"=r"(r3) : "r"(addr))

// ---------------- setup: split out_W into 2 fp16 levels ----------------
__global__ void k_wsplit(const float* __restrict__ outW){
  size_t i4 = (size_t)blockIdx.x*256 + threadIdx.x;
  float4 w = ((const float4*)outW)[i4];
  uint2 uh, um;
  split2h(make_float2(w.x,w.y), uh.x, um.x);
  split2h(make_float2(w.z,w.w), uh.y, um.y);
  ((uint2*)g_Wh)[i4] = uh;
  ((uint2*)g_Wm)[i4] = um;
}

// ---------------- setup: transpose decoder GRU weights ----------------
__global__ void k_wtrans(const float* __restrict__ dWih, const float* __restrict__ dWhh){
  int idx = blockIdx.x*256 + threadIdx.x;
  if(idx < 192*192){
    int k = idx/192, j = idx%192;
    g_wiT2[idx] = make_float2(dWih[(size_t)(2*j)*192+k], dWih[(size_t)(2*j+1)*192+k]);
  } else {
    int i2 = idx - 192*192;
    if(i2 < 128*192){
      int k = i2/192, j = i2%192;
      g_whT2[i2] = make_float2(dWhh[(size_t)(2*j)*128+k], dWhh[(size_t)(2*j+1)*128+k]);
    }
  }
}

// ---------------- encoder input projection ----------------
__global__ void __launch_bounds__(384,2) k_giall(const int* __restrict__ seq,
      const float* __restrict__ emb, const float* __restrict__ Wih,
      const float* __restrict__ bih){
  int g = threadIdx.x;
  float w[64];
  const float4* wp = (const float4*)(Wih + (size_t)g*64);
  #pragma unroll
  for(int i=0;i<16;i++){ float4 q=wp[i]; w[4*i]=q.x; w[4*i+1]=q.y; w[4*i+2]=q.z; w[4*i+3]=q.w; }
  float bias = bih[g];
  __shared__ float xs[2][64];
  const int ROWS = (SS*BB)/512;
  size_t base = (size_t)blockIdx.x * ROWS;
  if(g<64){ int tok0 = seq[base]; xs[0][g] = emb[(size_t)tok0*EE + g]; }
  __syncthreads();
  for(int r=0;r<ROWS;r++){
    int cur=r&1, nxt=cur^1;
    if(r+1<ROWS && g<64){
      int tok2 = seq[base+r+1];
      xs[nxt][g] = emb[(size_t)tok2*EE + g];
    }
    float a0=0,a1=0,a2=0,a3=0;
    #pragma unroll
    for(int k=0;k<64;k+=4){
      a0 += w[k]*xs[cur][k];     a1 += w[k+1]*xs[cur][k+1];
      a2 += w[k+2]*xs[cur][k+2]; a3 += w[k+3]*xs[cur][k+3];
    }
    g_gi[(base+r)*GG + g] = (a0+a1)+(a2+a3) + bias;
    __syncthreads();
  }
}

// ---------------- encoder recurrence ----------------
__global__ void __launch_bounds__(384,1) k_encrec(const float* __restrict__ Whh,
      const float* __restrict__ bhh){
  extern __shared__ float sm[];
  float* whh_s = sm;
  float* hs    = sm + 12288;
  float* ghs   = hs + 128;
  float* gis   = ghs + 384;
  int b = blockIdx.x;
  int g = threadIdx.x;
  float w[96];
  {
    const float4* wlo = (const float4*)(Whh + (size_t)g*128);
    #pragma unroll
    for(int i=0;i<24;i++){ float4 q=wlo[i]; w[4*i]=q.x; w[4*i+1]=q.y; w[4*i+2]=q.z; w[4*i+3]=q.w; }
    const float4* whi = (const float4*)(Whh + (size_t)g*128 + 96);
    #pragma unroll
    for(int i=0;i<8;i++) ((float4*)whh_s)[i*384 + g] = whi[i];
  }
  float bias = bhh[g];
  if(g<128) hs[g] = 0.0f;
  __syncthreads();

  float giv = g_gi[(size_t)b*GG + g];
  for(int s=0;s<SS;s++){
    float gi_next = 0.0f;
    if(s+1<SS) gi_next = g_gi[((size_t)(s+1)*BB + b)*GG + g];
    gis[g] = giv;
    float a0=0,a1=0,a2=0,a3=0;
    #pragma unroll
    for(int i=0;i<24;i++){
      float4 hv = ((float4*)hs)[i];
      a0 += w[4*i]*hv.x;   a1 += w[4*i+1]*hv.y;
      a2 += w[4*i+2]*hv.z; a3 += w[4*i+3]*hv.w;
    }
    #pragma unroll
    for(int i=0;i<8;i++){
      float4 wv = ((float4*)whh_s)[i*384 + g];
      float4 hv = ((float4*)hs)[24 + i];
      a0 += wv.x*hv.x; a1 += wv.y*hv.y; a2 += wv.z*hv.z; a3 += wv.w*hv.w;
    }
    ghs[g] = (a0+a1)+(a2+a3) + bias;
    __syncthreads();
    if(g<128){
      float rr = sig_acc(gis[g]       + ghs[g]);
      float zz = sig_acc(gis[128+g]   + ghs[128+g]);
      float nn = tanhf (gis[256+g] + rr*ghs[256+g]);
      float hn = (1.0f-zz)*nn + zz*hs[g];
      g_eoT[((size_t)b*SS + s)*HH + g] = hn;
      hs[g] = hn;
    }
    __syncthreads();
    giv = gi_next;
  }
  if(g<128) g_h[b*HH + g] = hs[g];
}

// ---------------- enc_proj ----------------
__global__ void __launch_bounds__(256,2) k_encproj(const float* __restrict__ attnW,
                                                   const float* __restrict__ attnb){
  int t = threadIdx.x;
  int j = t & 127, half = t >> 7;
  float w[64];
  const float4* wp = (const float4*)(attnW + (size_t)j*256 + 128 + half*64);
  #pragma unroll
  for(int i=0;i<16;i++){ float4 q=wp[i]; w[4*i]=q.x; w[4*i+1]=q.y; w[4*i+2]=q.z; w[4*i+3]=q.w; }
  float bias = attnb[j];
  __shared__ float xs[2][128];
  __shared__ float part[2][128];
  const int ROWS = (SS*BB)/512;
  size_t base = (size_t)blockIdx.x * ROWS;
  if(t<128) xs[0][t] = g_eoT[base*HH + t];
  __syncthreads();
  for(int r=0;r<ROWS;r++){
    int cur=r&1, nxt=cur^1;
    if(r+1<ROWS && t<128) xs[nxt][t] = g_eoT[(base+r+1)*HH + t];
    float a0=0,a1=0,a2=0,a3=0;
    const float* xp = &xs[cur][half*64];
    #pragma unroll
    for(int k=0;k<64;k+=4){
      a0+=w[k]*xp[k]; a1+=w[k+1]*xp[k+1]; a2+=w[k+2]*xp[k+2]; a3+=w[k+3]*xp[k+3];
    }
    part[half][j] = (a0+a1)+(a2+a3);
    __syncthreads();
    if(!half) g_epBS[(base+r)*HH + j] = part[0][j] + part[1][j] + bias;
    __syncthreads();
  }
}

// ---------------- per-b transpose enc_proj ----------------
__global__ void k_trP2(){
  __shared__ float tile[32][33];
  int b = blockIdx.z;
  int s0 = blockIdx.x*32, h0 = blockIdx.y*32;
  int tx = threadIdx.x, ty = threadIdx.y;
  #pragma unroll
  for(int i=0;i<32;i+=8)
    tile[ty+i][tx] = g_epBS[((size_t)b*SS + s0+ty+i)*HH + h0+tx];
  __syncthreads();
  #pragma unroll
  for(int i=0;i<32;i+=8)
    g_epT[((size_t)b*HH + h0+ty+i)*SS + s0+tx] = tile[tx][ty+i];
}

// ---------------- attention work (shared struct passed by kernel) ----------------
struct SAtt {
  float hs[128], hp[128], part[128], vsd[128];
  float ws[1024];
  float red[40];
  float4 cbuf[8][32];
};

__device__ void att_work(SAtt* S, int b, const float* __restrict__ attnW,
                         const float* __restrict__ attnv){
  int tid = threadIdx.x, lane = tid&31, warp = tid>>5;
  if(tid<128){ S->hs[tid] = g_h[b*HH + tid]; S->vsd[tid] = attnv[tid]; }
  __syncthreads();
  // hp = h @ attn_W[:, :128].T
  {
    int j = tid & 127, half = tid >> 7;
    const float4* wr = (const float4*)(attnW + (size_t)j*256 + half*64);
    const float* hb = &S->hs[half*64];
    float a = 0.0f;
    #pragma unroll
    for(int i=0;i<16;i++){
      float4 q = wr[i];
      a += q.x*hb[4*i] + q.y*hb[4*i+1] + q.z*hb[4*i+2] + q.w*hb[4*i+3];
    }
    if(half) S->part[j] = a;
    __syncthreads();
    if(!half) S->hp[j] = a + S->part[j];
    __syncthreads();
  }
  // scores
  {
    const float* base = g_epT + (size_t)b*HH*SS;
    float a0=0,a1=0,a2=0,a3=0;
    #pragma unroll 4
    for(int h=0;h<128;h++){
      float hpv = S->hp[h], vv = S->vsd[h];
      const float* p = base + (size_t)h*SS + tid;
      float e0 = p[0], e1 = p[256], e2 = p[512], e3 = p[768];
      a0 += tanh_fast(e0+hpv)*vv;
      a1 += tanh_fast(e1+hpv)*vv;
      a2 += tanh_fast(e2+hpv)*vv;
      a3 += tanh_fast(e3+hpv)*vv;
    }
    S->ws[tid]=a0; S->ws[tid+256]=a1; S->ws[tid+512]=a2; S->ws[tid+768]=a3;
  }
  __syncthreads();
  // softmax
  {
    float4 sc = ((float4*)S->ws)[tid];
    float m = fmaxf(fmaxf(sc.x,sc.y), fmaxf(sc.z,sc.w));
    #pragma unroll
    for(int o=16;o;o>>=1) m = fmaxf(m, __shfl_xor_sync(0xffffffffu,m,o));
    if(lane==0) S->red[warp] = m;
    __syncthreads();
    if(tid==0){ float mm=S->red[0]; for(int i=1;i<8;i++) mm=fmaxf(mm,S->red[i]); S->red[8]=mm; }
    __syncthreads();
    float M = S->red[8];
    float4 e;
    e.x=expf(sc.x-M); e.y=expf(sc.y-M); e.z=expf(sc.z-M); e.w=expf(sc.w-M);
    ((float4*)S->ws)[tid] = e;
    float ssum = (e.x+e.y)+(e.z+e.w);
    #pragma unroll
    for(int o=16;o;o>>=1) ssum += __shfl_xor_sync(0xffffffffu, ssum, o);
    if(lane==0) S->red[16+warp] = ssum;
    __syncthreads();
    if(tid==0){ float s2=0; for(int i=0;i<8;i++) s2+=S->red[16+i]; S->red[24]=s2; }
    __syncthreads();
  }
  float inv = 1.0f / S->red[24];
  // context -> S->part[0..127] and g_ctx
  {
    int hq = tid&31, sg = tid>>5;
    const float* base = g_eoT + (size_t)b*SS*HH;
    float4 acc = make_float4(0,0,0,0);
    #pragma unroll 4
    for(int i=0;i<128;i++){
      int s = sg + (i<<3);
      float wg = S->ws[s];
      float4 ev = ((const float4*)(base + (size_t)s*HH))[hq];
      acc.x += wg*ev.x; acc.y += wg*ev.y; acc.z += wg*ev.z; acc.w += wg*ev.w;
    }
    S->cbuf[sg][hq] = acc;
    __syncthreads();
    if(tid<32){
      float4 tot = S->cbuf[0][tid];
      #pragma unroll
      for(int g2=1;g2<8;g2++){
        float4 c = S->cbuf[g2][tid];
        tot.x+=c.x; tot.y+=c.y; tot.z+=c.z; tot.w+=c.w;
      }
      tot.x*=inv; tot.y*=inv; tot.z*=inv; tot.w*=inv;
      int h0 = tid*4;
      S->part[h0]=tot.x; S->part[h0+1]=tot.y; S->part[h0+2]=tot.z; S->part[h0+3]=tot.w;
      g_ctx[b*HH+h0]=tot.x; g_ctx[b*HH+h0+1]=tot.y;
      g_ctx[b*HH+h0+2]=tot.z; g_ctx[b*HH+h0+3]=tot.w;
    }
  }
  __syncthreads();
  // gh = Whh.h ; gic = Wih[:,64:].ctx (no biases)
  if(tid < 192){
    float g0=0,g1=0,c0=0,c1=0;
    #pragma unroll 4
    for(int k=0;k<128;k++){
      float2 wh2 = g_whT2[k*192 + tid];
      float2 wi2 = g_wiT2[(64+k)*192 + tid];
      float hv = S->hs[k], cv = S->part[k];
      g0 += wh2.x*hv; g1 += wh2.y*hv;
      c0 += wi2.x*cv; c1 += wi2.y*cv;
    }
    g_gh[b*GG+2*tid]=g0;  g_gh[b*GG+2*tid+1]=g1;
    g_gic[b*GG+2*tid]=c0; g_gic[b*GG+2*tid+1]=c1;
  }
}

// ---------------- setup attention (step 0) ----------------
__global__ void __launch_bounds__(256,1) k_att0(const float* __restrict__ attnW,
                                                const float* __restrict__ attnv){
  __shared__ SAtt satt;
  att_work(&satt, blockIdx.x, attnW, attnv);
}

// ---------------- decoder GRU (serial-path kernel, small) ----------------
__global__ void __launch_bounds__(256,4) k_gru(const int* __restrict__ seq,
      const float* __restrict__ emb, const float* __restrict__ dbih,
      const float* __restrict__ dbhh, int t){
  __shared__ float embs[64], gi[384], gh[384], hold[128], hnew[128], ctxs[128];
  __shared__ float sv[8]; __shared__ int si8[8]; __shared__ int stok;
  int b = blockIdx.x, tid = threadIdx.x;
  int lane = tid&31, warp = tid>>5;
  if(t == 0){
    if(tid==0) stok = seq[b];
  } else {
    float v=-3.4e38f; int ix=0x7fffffff;
    for(int idx=tid; idx<NTILES2; idx+=256){
      float pv = g_pval[b*1024+idx]; int pi = g_pidx[b*1024+idx];
      if(pv>v || (pv==v && pi<ix)){ v=pv; ix=pi; }
    }
    #pragma unroll
    for(int o=16;o;o>>=1){
      float ov=__shfl_xor_sync(0xffffffffu,v,o); int oi=__shfl_xor_sync(0xffffffffu,ix,o);
      if(ov>v || (ov==v && oi<ix)){ v=ov; ix=oi; }
    }
    if(lane==0){ sv[warp]=v; si8[warp]=ix; }
    __syncthreads();
    if(tid==0){
      float bv=sv[0]; int bx=si8[0];
      for(int i=1;i<8;i++) if(sv[i]>bv || (sv[i]==bv && si8[i]<bx)){ bv=sv[i]; bx=si8[i]; }
      stok = bx;
    }
  }
  if(tid==0) g_tilectr = 0;     // reset logits tile pool (all CTAs write 0)
  __syncthreads();
  if(tid < 64) embs[tid] = emb[(size_t)stok*EE + tid];
  if(tid < 128){ hold[tid] = g_h[b*HH + tid]; ctxs[tid] = g_ctx[b*HH + tid]; }
  __syncthreads();
  if(tid < 192){
    float a0 = dbih[2*tid]   + g_gic[b*GG+2*tid];
    float a1 = dbih[2*tid+1] + g_gic[b*GG+2*tid+1];
    #pragma unroll 8
    for(int k=0;k<64;k++){
      float2 w = g_wiT2[k*192 + tid];
      float x = embs[k];
      a0 += w.x*x; a1 += w.y*x;
    }
    gi[2*tid]=a0; gi[2*tid+1]=a1;
    gh[2*tid]   = dbhh[2*tid]   + g_gh[b*GG+2*tid];
    gh[2*tid+1] = dbhh[2*tid+1] + g_gh[b*GG+2*tid+1];
  }
  __syncthreads();
  if(tid < 128){
    float rr = sig_acc(gi[tid]     + gh[tid]);
    float zz = sig_acc(gi[128+tid] + gh[128+tid]);
    float nn = tanhf (gi[256+tid] + rr*gh[256+tid]);
    float hv = (1.0f-zz)*nn + zz*hold[tid];
    g_h[b*HH + tid] = hv;
    hnew[tid] = hv;
  }
  __syncthreads();
  if(tid < 128){
    float f0, f1;
    if(tid < 64){ f0 = hnew[2*tid]; f1 = hnew[2*tid+1]; }
    else        { f0 = ctxs[2*tid-128]; f1 = ctxs[2*tid-127]; }
    uint32_t h,m;
    split2h(make_float2(f0,f1), h, m);
    g_xh[b*128+tid]=h; g_xm[b*128+tid]=m;
  }
}

// ---------------- fused: attention(t+1) overlapped with logits(t) tile pool ----------------
#define BSTR 528u
#define SPL (32u*BSTR)          // 16896 per split
#define BUFB (2u*SPL)           // 33792 per buffer (h+m)
#define LOG_DYN (2*BUFB)        // 67584
__global__ void __launch_bounds__(256,2) k_fused(const float* __restrict__ attnW,
      const float* __restrict__ attnv, const float* __restrict__ outb,
      float* __restrict__ out, int t, int do_att){
  extern __shared__ char dyn[];
  __shared__ SAtt satt;
  __shared__ int s_tile;
  int cta = blockIdx.x, tid = threadIdx.x;
  if(do_att && cta < 128) att_work(&satt, cta, attnW, attnv);

  // ---- logits tile pool ----
  uint32_t sb = s2u(dyn);
  int wid = tid>>5, lane = tid&31;
  int r = lane>>2, tig = lane&3;
  int b0 = wid*16 + r, b1 = b0 + 8;
  uint32_t lrow = (uint32_t)(lane&7) + (uint32_t)((lane>>4)<<3);
  uint32_t lkadd = (uint32_t)(((lane>>3)&1)<<4);
  float* outRow = out + (size_t)t*BB*VV;
  const float INVS = 1.0f/2048.0f;

  __syncthreads();
  if(tid==0) s_tile = atomicAdd(&g_tilectr, 1);
  __syncthreads();
  int cur = s_tile;
  if(cur < NTILES2){
    const char* sH = (const char*)g_Wh + (size_t)cur*NT2*512;
    const char* sM = (const char*)g_Wm + (size_t)cur*NT2*512;
    #pragma unroll
    for(int j=0;j<4;j++){
      int idx = tid + j*256;
      uint32_t off = (uint32_t)(idx>>5)*BSTR + (uint32_t)(idx&31)*16u;
      cpasync16(sb + off,       sH + (size_t)idx*16);
      cpasync16(sb + SPL + off, sM + (size_t)idx*16);
    }
  }
  asm volatile("cp.async.commit_group;" ::: "memory");

  int bufi = 0;
  while(cur < NTILES2){
    __syncthreads();
    if(tid==0) s_tile = atomicAdd(&g_tilectr, 1);
    __syncthreads();
    int nxt = s_tile;
    uint32_t curb = sb + (bufi ? BUFB : 0u);
    uint32_t nxtb = sb + (bufi ? 0u : BUFB);
    if(nxt < NTILES2){
      const char* sH = (const char*)g_Wh + (size_t)nxt*NT2*512;
      const char* sM = (const char*)g_Wm + (size_t)nxt*NT2*512;
      #pragma unroll
      for(int j=0;j<4;j++){
        int idx = tid + j*256;
        uint32_t off = (uint32_t)(idx>>5)*BSTR + (uint32_t)(idx&31)*16u;
        cpasync16(nxtb + off,       sH + (size_t)idx*16);
        cpasync16(nxtb + SPL + off, sM + (size_t)idx*16);
      }
    }
    asm volatile("cp.async.commit_group;" ::: "memory");
    asm volatile("cp.async.wait_group 1;" ::: "memory");
    __syncthreads();

    int v0 = cur*NT2;
    float c1[4][4], c2[4][4];
    #pragma unroll
    for(int i=0;i<4;i++){
      c1[i][0]=0.f;c1[i][1]=0.f;c1[i][2]=0.f;c1[i][3]=0.f;
      c2[i][0]=0.f;c2[i][1]=0.f;c2[i][2]=0.f;c2[i][3]=0.f;
    }
    #pragma unroll
    for(int kc=0;kc<2;kc++){
      uint32_t ah[8][4], am[8][4];
      int base0 = b0*128 + kc*64 + tig;
      int base1 = b1*128 + kc*64 + tig;
      #pragma unroll
      for(int ks=0;ks<8;ks++){
        int i0 = base0 + ks*8, i1 = base1 + ks*8;
        ah[ks][0]=g_xh[i0]; ah[ks][1]=g_xh[i1]; ah[ks][2]=g_xh[i0+4]; ah[ks][3]=g_xh[i1+4];
        am[ks][0]=g_xm[i0]; am[ks][1]=g_xm[i1]; am[ks][2]=g_xm[i0+4]; am[ks][3]=g_xm[i1+4];
      }
      #pragma unroll
      for(int ks=0;ks<8;ks++){
        uint32_t kb = (uint32_t)(kc*128 + ks*16)*2u;
        #pragma unroll
        for(int nsp=0;nsp<2;nsp++){
          uint32_t rowoff = ((uint32_t)nsp*16u + lrow)*BSTR + kb + lkadd;
          uint32_t h0a,h1a,h0b,h1b, m0a,m1a,m0b,m1b;
          LDSM4(h0a,h1a,h0b,h1b, curb + rowoff);
          LDSM4(m0a,m1a,m0b,m1b, curb + SPL + rowoff);
          MMA(c1[2*nsp],   ah[ks], h0a,h1a);
          MMA(c2[2*nsp],   ah[ks], m0a,m1a);
          MMA(c2[2*nsp],   am[ks], h0a,h1a);
          MMA(c1[2*nsp+1], ah[ks], h0b,h1b);
          MMA(c2[2*nsp+1], ah[ks], m0b,m1b);
          MMA(c2[2*nsp+1], am[ks], h0b,h1b);
        }
      }
    }
    // epilogue
    float bv0=-3.4e38f, bv1=-3.4e38f; int bi0=0x7fffffff, bi1=0x7fffffff;
    #pragma unroll
    for(int ns=0;ns<4;ns++){
      int n = ns*8 + tig*2;
      float2 bb = *(const float2*)(outb + v0 + n);
      float f0 = c1[ns][0] + c2[ns][0]*INVS + bb.x;
      float f1 = c1[ns][1] + c2[ns][1]*INVS + bb.y;
      float f2 = c1[ns][2] + c2[ns][2]*INVS + bb.x;
      float f3 = c1[ns][3] + c2[ns][3]*INVS + bb.y;
      if(f0>bv0){bv0=f0;bi0=v0+n;}
      if(f1>bv0){bv0=f1;bi0=v0+n+1;}
      if(f2>bv1){bv1=f2;bi1=v0+n;}
      if(f3>bv1){bv1=f3;bi1=v0+n+1;}
      *(float2*)(outRow + (size_t)b0*VV + v0 + n) = make_float2(f0,f1);
      *(float2*)(outRow + (size_t)b1*VV + v0 + n) = make_float2(f2,f3);
    }
    #pragma unroll
    for(int o=1;o<4;o<<=1){
      float ov0=__shfl_xor_sync(0xffffffffu,bv0,o); int oi0=__shfl_xor_sync(0xffffffffu,bi0,o);
      float ov1=__shfl_xor_sync(0xffffffffu,bv1,o); int oi1=__shfl_xor_sync(0xffffffffu,bi1,o);
      if(ov0>bv0||(ov0==bv0&&oi0<bi0)){bv0=ov0;bi0=oi0;}
      if(ov1>bv1||(ov1==bv1&&oi1<bi1)){bv1=ov1;bi1=oi1;}
    }
    if(tig==0){
      g_pval[b0*1024 + cur]=bv0; g_pidx[b0*1024 + cur]=bi0;
      g_pval[b1*1024 + cur]=bv1; g_pidx[b1*1024 + cur]=bi1;
    }
    cur = nxt;
    bufi ^= 1;
  }
}

// ---------------- launch ----------------
extern "C" void kernel_launch(void* const* d_in, const int* in_sizes, int n_in,
                              void* d_out, int out_size) {
  const int*   seq     = (const int*)  d_in[0];
  const float* emb     = (const float*)d_in[2];
  const float* encWih  = (const float*)d_in[3];
  const float* encWhh  = (const float*)d_in[4];
  const float* encbih  = (const float*)d_in[5];
  const float* encbhh  = (const float*)d_in[6];
  const float* attnW   = (const float*)d_in[7];
  const float* attnb   = (const float*)d_in[8];
  const float* attnv   = (const float*)d_in[9];
  const float* dWih    = (const float*)d_in[10];
  const float* dWhh    = (const float*)d_in[11];
  const float* dbih    = (const float*)d_in[12];
  const float* dbhh    = (const float*)d_in[13];
  const float* outW    = (const float*)d_in[14];
  const float* outb    = (const float*)d_in[15];
  float* out = (float*)d_out;

  const int ENC_SMEM = (12288 + 128 + 384 + 384) * 4;
  cudaFuncSetAttribute(k_encrec, cudaFuncAttributeMaxDynamicSharedMemorySize, ENC_SMEM);
  cudaFuncSetAttribute(k_fused,  cudaFuncAttributeMaxDynamicSharedMemorySize, LOG_DYN);

  // setup
  k_wsplit<<<8000, 256>>>(outW);
  k_wtrans<<<240, 256>>>(dWih, dWhh);
  k_giall<<<512, 384>>>(seq, emb, encWih, encbih);
  k_encrec<<<128, 384, ENC_SMEM>>>(encWhh, encbhh);
  k_encproj<<<512, 256>>>(attnW, attnb);
  k_trP2<<<dim3(32,4,128), dim3(32,8)>>>();
  k_att0<<<128, 256>>>(attnW, attnv);   // attention for step 0

  // decode: 2 kernels per step; logits(t) overlaps attention(t+1)
  for(int t=0; t<TT; t++){
    k_gru<<<128, 256>>>(seq, emb, dbih, dbhh, t);
    k_fused<<<256, 256, LOG_DYN>>>(attnW, attnv, outb, out, t, (t < TT-1) ? 1 : 0);
  }
}